// round 9
// baseline (speedup 1.0000x reference)
#include <cuda_runtime.h>
#include <cstdint>
#include <math.h>

#define BB 2
#define SS 1024
#define DD 1024
#define HH 16
#define HD 64
#define LL 4
#define VV 32000
#define NROW (BB * SS)   // 2048
#define NT_OUT (VV / 128)   // 250 N-tiles for logits
#define MT_A   (NROW / 128) // 16 M-tiles
#define KC_D   (DD / 32)    // 32 K-chunks

// ---------------- scratch (static device globals; no allocs allowed) --------
__device__ float g_x[NROW * DD];
__device__ float g_q[NROW * DD];
__device__ float g_k[NROW * DD];
__device__ float g_v[NROW * DD];
__device__ float g_ctx[NROW * DD];
__device__ float g_attn[NROW * DD];
// fragment-major prelayout buffers
__device__ float g_afrag[MT_A * KC_D * 4096];          // 8 MB
__device__ float g_wfrag[(size_t)NT_OUT * KC_D * 4096];// 131 MB

__device__ __forceinline__ float tf32r(float x) {
    float r; asm("cvt.rna.tf32.f32 %0, %1;" : "=f"(r) : "f"(x)); return r;
}

// =================== tf32 mma.sync GEMM, fragment-major smem ================
// (per-layer kernel: CTA 128x128, BK=32, 2 stages, warp tile 64x32)

#define GEMM_SMEM_FLOATS 16384
#define GEMM_SMEM_BYTES  (GEMM_SMEM_FLOATS * 4)

__device__ __forceinline__ void gemm_core(
    const float* __restrict__ A, const float* __restrict__ W,
    const float* __restrict__ bias, float* __restrict__ C,
    int M, int N, int K, int bm, int bn, float* sm)
{
    const int t    = threadIdx.x;
    const int lane = t & 31;
    const int wid  = t >> 5;
    const int g    = lane >> 2;
    const int tg   = lane & 3;
    const int wm   = (wid & 1) * 64;
    const int wn   = (wid >> 1) * 32;

    float acc[4][4][4];
#pragma unroll
    for (int mf = 0; mf < 4; mf++)
#pragma unroll
        for (int nf = 0; nf < 4; nf++)
#pragma unroll
            for (int r = 0; r < 4; r++) acc[mf][nf][r] = 0.0f;

    int aBase[4], bBase[4];
#pragma unroll
    for (int i = 0; i < 4; i++) {
        int idx = t + i * 256;
        {
            int row = idx >> 3, c4 = idx & 7;
            int mi = row >> 4, m16 = row & 15;
            int ga = m16 & 7, rA = m16 >> 3;
            int ki = c4 >> 1, khi = c4 & 1;
            aBase[i] = ((mi * 4 + ki) * 32) * 4 + (rA + 2 * khi);
            aBase[i] |= (ga << 24) | (ki << 28);
        }
        {
            int rowk = idx >> 5, c4 = idx & 31;
            int n0 = c4 * 4;
            int ki = rowk >> 3, kk = rowk & 7;
            int tgb = kk & 3, hi = kk >> 2;
            int ni = n0 >> 3, g0 = n0 & 7;
            int swz = ((ni & 3) << 3) ^ (((ni >> 2) & 3) << 1);
            int ln0 = g0 * 4 + tgb;
            bBase[i] = ((ni * 4 + ki) * 32) * 2 + hi;
            bBase[i] |= (ln0 << 20) | (swz << 26);
        }
    }

    const int nkt = K >> 5;

    const float* aPtr[4];
    const float* bPtr[4];
#pragma unroll
    for (int i = 0; i < 4; i++) {
        int idx = t + i * 256;
        aPtr[i] = A + (size_t)(bm + (idx >> 3)) * K + (idx & 7) * 4;
        bPtr[i] = W + (size_t)(idx >> 5) * N + bn + (idx & 31) * 4;
    }

    auto storeA = [&](int s, int i, float4 v) {
        int meta = aBase[i];
        int base = meta & 0xFFFFF;
        int ga   = (meta >> 24) & 7;
        int ki   = (meta >> 28) & 3;
        float* dst = sm + s * 4096;
        float vv[4] = {tf32r(v.x), tf32r(v.y), tf32r(v.z), tf32r(v.w)};
#pragma unroll
        for (int e = 0; e < 4; e++) {
            int lp = (ga * 4 + e) ^ ki;
            dst[base + lp * 4] = vv[e];
        }
    };
    auto storeB = [&](int s, int i, float4 v) {
        int meta = bBase[i];
        int base = meta & 0xFFFFF;
        int ln0  = (meta >> 20) & 63;
        int swz  = (meta >> 26) & 31;
        float* dst = sm + 8192 + s * 4096;
        float vv[4] = {tf32r(v.x), tf32r(v.y), tf32r(v.z), tf32r(v.w)};
#pragma unroll
        for (int e = 0; e < 4; e++) {
            int lp = (ln0 + 4 * e) ^ swz;
            dst[base + lp * 2] = vv[e];
        }
    };

#pragma unroll
    for (int i = 0; i < 4; i++) {
        storeA(0, i, *(const float4*)aPtr[i]);
        storeB(0, i, *(const float4*)bPtr[i]);
    }
    __syncthreads();

    int bswz[4];
#pragma unroll
    for (int nf = 0; nf < 4; nf++) {
        int ni = (wid >> 1) * 4 + nf;
        bswz[nf] = lane ^ ((ni & 3) << 3) ^ (((ni >> 2) & 3) << 1);
    }

    for (int kt = 0; kt < nkt; kt++) {
        const int cur = kt & 1;
        float4 pa[4], pb[4];
        const bool pf = (kt + 1 < nkt);
        if (pf) {
            const size_t ko = (size_t)(kt + 1) << 5;
#pragma unroll
            for (int i = 0; i < 4; i++) {
                pa[i] = *(const float4*)(aPtr[i] + ko);
                pb[i] = *(const float4*)(bPtr[i] + ko * (size_t)N);
            }
        }

        const float* asb = sm + cur * 4096;
        const float* bsb = sm + 8192 + cur * 4096;
#pragma unroll
        for (int ki = 0; ki < 4; ki++) {
            float4 afv[4];
            float2 bfv[4];
#pragma unroll
            for (int mf = 0; mf < 4; mf++) {
                int mi = (wid & 1) * 4 + mf;
                afv[mf] = *(const float4*)(asb + ((mi * 4 + ki) * 32 + (lane ^ ki)) * 4);
            }
#pragma unroll
            for (int nf = 0; nf < 4; nf++) {
                int ni = (wid >> 1) * 4 + nf;
                bfv[nf] = *(const float2*)(bsb + ((ni * 4 + ki) * 32 + bswz[nf]) * 2);
            }
#pragma unroll
            for (int mf = 0; mf < 4; mf++)
#pragma unroll
                for (int nf = 0; nf < 4; nf++) {
                    asm volatile(
                        "mma.sync.aligned.m16n8k8.row.col.f32.tf32.tf32.f32 "
                        "{%0,%1,%2,%3}, {%4,%5,%6,%7}, {%8,%9}, {%0,%1,%2,%3};"
                        : "+f"(acc[mf][nf][0]), "+f"(acc[mf][nf][1]),
                          "+f"(acc[mf][nf][2]), "+f"(acc[mf][nf][3])
                        : "r"(__float_as_uint(afv[mf].x)), "r"(__float_as_uint(afv[mf].y)),
                          "r"(__float_as_uint(afv[mf].z)), "r"(__float_as_uint(afv[mf].w)),
                          "r"(__float_as_uint(bfv[nf].x)), "r"(__float_as_uint(bfv[nf].y)));
                }
        }

        if (pf) {
            const int nxt = 1 - cur;
#pragma unroll
            for (int i = 0; i < 4; i++) {
                storeA(nxt, i, pa[i]);
                storeB(nxt, i, pb[i]);
            }
        }
        __syncthreads();
    }

#pragma unroll
    for (int mf = 0; mf < 4; mf++) {
        const int r0 = bm + wm + mf * 16 + g;
        const int r1 = r0 + 8;
#pragma unroll
        for (int nf = 0; nf < 4; nf++) {
            const int col = bn + wn + nf * 8 + tg * 2;
            const float b0 = bias[col], b1 = bias[col + 1];
            float2 v0 = make_float2(acc[mf][nf][0] + b0, acc[mf][nf][1] + b1);
            float2 v1 = make_float2(acc[mf][nf][2] + b0, acc[mf][nf][3] + b1);
            *(float2*)(C + (size_t)r0 * N + col) = v0;
            *(float2*)(C + (size_t)r1 * N + col) = v1;
        }
    }
}

__global__ void __launch_bounds__(256)
gemm_mma(const float* __restrict__ A, const float* __restrict__ W,
         const float* __restrict__ bias, float* __restrict__ C,
         int M, int N, int K)
{
    extern __shared__ float sm[];
    gemm_core(A, W, bias, C, M, N, K, blockIdx.x * 128, blockIdx.y * 128, sm);
}

__global__ void __launch_bounds__(256)
gemm_mma_qkv(const float* __restrict__ A,
             const float* __restrict__ qw, const float* __restrict__ kw,
             const float* __restrict__ vw,
             const float* __restrict__ qb, const float* __restrict__ kb,
             const float* __restrict__ vb,
             float* __restrict__ qo, float* __restrict__ ko, float* __restrict__ vo)
{
    extern __shared__ float sm[];
    const float* W    = (blockIdx.z == 0) ? qw : (blockIdx.z == 1) ? kw : vw;
    const float* bias = (blockIdx.z == 0) ? qb : (blockIdx.z == 1) ? kb : vb;
    float*       C    = (blockIdx.z == 0) ? qo : (blockIdx.z == 1) ? ko : vo;
    gemm_core(A, W, bias, C, NROW, DD, DD, blockIdx.x * 128, blockIdx.y * 128, sm);
}

// =================== prelayout kernels (scatter ONCE into gmem) =============
__global__ void __launch_bounds__(256)
prelayout_A(const float* __restrict__ A, float* __restrict__ out, int K)
{
    const int kc = blockIdx.x;
    const int mt = blockIdx.y;
    const int t  = threadIdx.x;
    float* dst = out + ((size_t)mt * gridDim.x + kc) * 4096;
#pragma unroll
    for (int i = 0; i < 4; i++) {
        int idx = t + i * 256;
        int row = idx >> 3, c4 = idx & 7;
        int mi = row >> 4, m16 = row & 15;
        int ga = m16 & 7, rA = m16 >> 3;
        int ki = c4 >> 1, khi = c4 & 1;
        int base = ((mi * 4 + ki) * 32) * 4 + (rA + 2 * khi);
        float4 v = *(const float4*)(A + (size_t)(mt * 128 + row) * K + kc * 32 + c4 * 4);
        float vv[4] = {tf32r(v.x), tf32r(v.y), tf32r(v.z), tf32r(v.w)};
#pragma unroll
        for (int e = 0; e < 4; e++) {
            int lp = (ga * 4 + e) ^ ki;
            dst[base + lp * 4] = vv[e];
        }
    }
}

__global__ void __launch_bounds__(256)
prelayout_W(const float* __restrict__ W, float* __restrict__ out, int N)
{
    const int kc = blockIdx.x;
    const int nt = blockIdx.y;
    const int t  = threadIdx.x;
    float* dst = out + ((size_t)nt * gridDim.x + kc) * 4096;
#pragma unroll
    for (int i = 0; i < 4; i++) {
        int idx = t + i * 256;
        int rowk = idx >> 5, c4 = idx & 31;
        int n0 = c4 * 4;
        int ki = rowk >> 3, kk = rowk & 7;
        int tgb = kk & 3, hi = kk >> 2;
        int ni = n0 >> 3, g0 = n0 & 7;
        int swz = ((ni & 3) << 3) ^ (((ni >> 2) & 3) << 1);
        int ln0 = g0 * 4 + tgb;
        int base = ((ni * 4 + ki) * 32) * 2 + hi;
        float4 v = *(const float4*)(W + (size_t)(kc * 32 + rowk) * N + nt * 128 + n0);
        float vv[4] = {tf32r(v.x), tf32r(v.y), tf32r(v.z), tf32r(v.w)};
#pragma unroll
        for (int e = 0; e < 4; e++) {
            int lp = (ln0 + 4 * e) ^ swz;
            dst[base + lp * 2] = vv[e];
        }
    }
}

// =================== GEMM on prelaid fragment-major operands ================
__global__ void __launch_bounds__(256)
gemm_pre(const float* __restrict__ afrag, const float* __restrict__ wfrag,
         const float* __restrict__ bias, float* __restrict__ C,
         int N, int nkc)
{
    extern __shared__ float sm[];
    const int t    = threadIdx.x;
    const int lane = t & 31;
    const int wid  = t >> 5;
    const int g    = lane >> 2;
    const int tg   = lane & 3;
    const int mt   = blockIdx.x;
    const int nt   = blockIdx.y;
    const int wm   = (wid & 1) * 64;
    const int wn   = (wid >> 1) * 32;

    float acc[4][4][4];
#pragma unroll
    for (int mf = 0; mf < 4; mf++)
#pragma unroll
        for (int nf = 0; nf < 4; nf++)
#pragma unroll
            for (int r = 0; r < 4; r++) acc[mf][nf][r] = 0.0f;

    const float* aSrc = afrag + (size_t)mt * nkc * 4096;
    const float* bSrc = wfrag + (size_t)nt * nkc * 4096;

#pragma unroll
    for (int i = 0; i < 4; i++) {
        int o4 = (t + i * 256) * 4;
        *(float4*)(sm + o4)        = *(const float4*)(aSrc + o4);
        *(float4*)(sm + 8192 + o4) = *(const float4*)(bSrc + o4);
    }
    __syncthreads();

    int bswz[4];
#pragma unroll
    for (int nf = 0; nf < 4; nf++) {
        int ni = (wid >> 1) * 4 + nf;
        bswz[nf] = lane ^ ((ni & 3) << 3) ^ (((ni >> 2) & 3) << 1);
    }

    for (int kt = 0; kt < nkc; kt++) {
        const int cur = kt & 1;
        float4 pa[4], pb[4];
        const bool pf = (kt + 1 < nkc);
        if (pf) {
            const float* an = aSrc + (size_t)(kt + 1) * 4096;
            const float* bn = bSrc + (size_t)(kt + 1) * 4096;
#pragma unroll
            for (int i = 0; i < 4; i++) {
                int o4 = (t + i * 256) * 4;
                pa[i] = *(const float4*)(an + o4);
                pb[i] = *(const float4*)(bn + o4);
            }
        }

        const float* asb = sm + cur * 4096;
        const float* bsb = sm + 8192 + cur * 4096;
#pragma unroll
        for (int ki = 0; ki < 4; ki++) {
            float4 afv[4];
            float2 bfv[4];
#pragma unroll
            for (int mf = 0; mf < 4; mf++) {
                int mi = (wid & 1) * 4 + mf;
                afv[mf] = *(const float4*)(asb + ((mi * 4 + ki) * 32 + (lane ^ ki)) * 4);
            }
#pragma unroll
            for (int nf = 0; nf < 4; nf++) {
                int ni = (wid >> 1) * 4 + nf;
                bfv[nf] = *(const float2*)(bsb + ((ni * 4 + ki) * 32 + bswz[nf]) * 2);
            }
#pragma unroll
            for (int mf = 0; mf < 4; mf++)
#pragma unroll
                for (int nf = 0; nf < 4; nf++) {
                    asm volatile(
                        "mma.sync.aligned.m16n8k8.row.col.f32.tf32.tf32.f32 "
                        "{%0,%1,%2,%3}, {%4,%5,%6,%7}, {%8,%9}, {%0,%1,%2,%3};"
                        : "+f"(acc[mf][nf][0]), "+f"(acc[mf][nf][1]),
                          "+f"(acc[mf][nf][2]), "+f"(acc[mf][nf][3])
                        : "r"(__float_as_uint(afv[mf].x)), "r"(__float_as_uint(afv[mf].y)),
                          "r"(__float_as_uint(afv[mf].z)), "r"(__float_as_uint(afv[mf].w)),
                          "r"(__float_as_uint(bfv[nf].x)), "r"(__float_as_uint(bfv[nf].y)));
                }
        }

        if (pf) {
            const int nxt = 1 - cur;
#pragma unroll
            for (int i = 0; i < 4; i++) {
                int o4 = (t + i * 256) * 4;
                *(float4*)(sm + nxt * 4096 + o4)        = pa[i];
                *(float4*)(sm + 8192 + nxt * 4096 + o4) = pb[i];
            }
        }
        __syncthreads();
    }

#pragma unroll
    for (int mf = 0; mf < 4; mf++) {
        const int r0 = mt * 128 + wm + mf * 16 + g;
        const int r1 = r0 + 8;
#pragma unroll
        for (int nf = 0; nf < 4; nf++) {
            const int col = nt * 128 + wn + nf * 8 + tg * 2;
            const float b0 = bias[col], b1 = bias[col + 1];
            float2 v0 = make_float2(acc[mf][nf][0] + b0, acc[mf][nf][1] + b1);
            float2 v1 = make_float2(acc[mf][nf][2] + b0, acc[mf][nf][3] + b1);
            *(float2*)(C + (size_t)r0 * N + col) = v0;
            *(float2*)(C + (size_t)r1 * N + col) = v1;
        }
    }
}

// ---------------- embedding + sinusoidal positional encoding ---------------
__global__ void embed_kernel(const int* __restrict__ tokens,
                             const float* __restrict__ emb,
                             float* __restrict__ x)
{
    int row = blockIdx.x;
    int pos = row & (SS - 1);
    int tok = tokens[row];
    const float* e = emb + (size_t)tok * DD;
    float* xr = x + (size_t)row * DD;
    const float c = -logf(10000.0f) / (float)DD;
    for (int d = threadIdx.x; d < DD; d += blockDim.x) {
        int i = d >> 1;
        float ang = (float)pos * expf((float)(2 * i) * c);
        float pe = (d & 1) ? cosf(ang) : sinf(ang);
        xr[d] = e[d] + pe;
    }
}

// ---------------- causal flash attention, 2 threads per query row ----------
// grid: (S/128, H, B); 256 threads; thread pair (2t, 2t+1) = one query row,
// each thread owns 32 of the 64 head dims. Pair-uniform control flow.
__global__ void __launch_bounds__(256)
attn_kernel(const float* __restrict__ Q, const float* __restrict__ K,
            const float* __restrict__ V, float* __restrict__ O)
{
    __shared__ float Ks[32][64];
    __shared__ float Vs[32][64];

    const int b = blockIdx.z;
    const int h = blockIdx.y;
    const int tid = threadIdx.x;
    const int row = tid >> 1;                         // 0..127
    const int half = tid & 1;                         // 0/1
    const int doff = half * 32;
    const int qi = blockIdx.x * 128 + row;
    const size_t base = (size_t)(b * SS) * DD + (size_t)h * HD;

    float q[32];
    {
        const float* qrow = Q + base + (size_t)qi * DD + doff;
#pragma unroll
        for (int d = 0; d < 32; d += 4) {
            float4 v = *(const float4*)(qrow + d);
            q[d] = v.x; q[d+1] = v.y; q[d+2] = v.z; q[d+3] = v.w;
        }
    }

    float o[32];
#pragma unroll
    for (int d = 0; d < 32; d++) o[d] = 0.0f;
    float m = -1e30f, l = 0.0f;

    const int kend = blockIdx.x * 128 + 128;
    for (int kt = 0; kt < kend; kt += 32) {
        // cooperative load: K+V tiles 32x64 = 512 float4 each; 256 thr x 2
#pragma unroll
        for (int i = 0; i < 2; i++) {
            int idx4 = tid + i * 256;                 // 0..511
            int r = idx4 >> 4;
            int c = (idx4 & 15) * 4;
            size_t gaddr = base + (size_t)(kt + r) * DD + c;
            *(float4*)&Ks[r][c] = *(const float4*)(K + gaddr);
            *(float4*)&Vs[r][c] = *(const float4*)(V + gaddr);
        }
        __syncthreads();

        const int jmax = qi - kt + 1;                 // pair-uniform
        float sv[32];
        float tmax = -1e30f;
#pragma unroll
        for (int j = 0; j < 32; j++) {
            float s = 0.0f;
#pragma unroll
            for (int d = 0; d < 32; d++) s += q[d] * Ks[j][doff + d];
            s += __shfl_xor_sync(0xFFFFFFFFu, s, 1);  // combine halves
            s *= 0.125f;
            sv[j] = (j < jmax) ? s : -1e30f;
            tmax = fmaxf(tmax, sv[j]);
        }
        float nm = fmaxf(m, tmax);
        float corr = __expf(m - nm);
        l *= corr;
#pragma unroll
        for (int d = 0; d < 32; d++) o[d] *= corr;
#pragma unroll
        for (int j = 0; j < 32; j++) {
            float p = __expf(sv[j] - nm);
            l += p;
#pragma unroll
            for (int d = 0; d < 32; d++)
                o[d] += p * Vs[j][doff + d];
        }
        m = nm;
        __syncthreads();
    }

    float inv = 1.0f / l;
    float* orow = O + base + (size_t)qi * DD + doff;
#pragma unroll
    for (int d = 0; d < 32; d += 4) {
        float4 v;
        v.x = o[d] * inv; v.y = o[d+1] * inv;
        v.z = o[d+2] * inv; v.w = o[d+3] * inv;
        *(float4*)(orow + d) = v;
    }
}

// ---------------- residual add + layernorm (in place on x) ----------------
__global__ void __launch_bounds__(256)
ln_res_kernel(float* __restrict__ x, const float* __restrict__ res,
              const float* __restrict__ g, const float* __restrict__ beta)
{
    __shared__ float red[256];
    const int row = blockIdx.x;
    const int tid = threadIdx.x;
    float* xr = x + (size_t)row * DD;
    const float* rr = res + (size_t)row * DD;

    float y[4];
    float s = 0.0f;
#pragma unroll
    for (int i = 0; i < 4; i++) {
        int d = tid + i * 256;
        y[i] = xr[d] + rr[d];
        s += y[i];
    }
    red[tid] = s; __syncthreads();
    for (int off = 128; off > 0; off >>= 1) {
        if (tid < off) red[tid] += red[tid + off];
        __syncthreads();
    }
    float mu = red[0] * (1.0f / (float)DD);
    __syncthreads();

    float vs = 0.0f;
#pragma unroll
    for (int i = 0; i < 4; i++) {
        float d2 = y[i] - mu;
        vs += d2 * d2;
    }
    red[tid] = vs; __syncthreads();
    for (int off = 128; off > 0; off >>= 1) {
        if (tid < off) red[tid] += red[tid + off];
        __syncthreads();
    }
    float var = red[0] * (1.0f / (float)DD);
    float inv = rsqrtf(var + 1e-5f);

#pragma unroll
    for (int i = 0; i < 4; i++) {
        int d = tid + i * 256;
        xr[d] = (y[i] - mu) * inv * g[d] + beta[d];
    }
}

// ---------------------------------------------------------------------------
extern "C" void kernel_launch(void* const* d_in, const int* in_sizes, int n_in,
                              void* d_out, int out_size)
{
    const int*   tokens = (const int*)  d_in[0];
    const float* emb    = (const float*)d_in[1];
    const float* qw     = (const float*)d_in[2];
    const float* qb     = (const float*)d_in[3];
    const float* kw     = (const float*)d_in[4];
    const float* kb     = (const float*)d_in[5];
    const float* vw     = (const float*)d_in[6];
    const float* vb     = (const float*)d_in[7];
    const float* ow     = (const float*)d_in[8];
    const float* ob     = (const float*)d_in[9];
    const float* ln_g   = (const float*)d_in[10];
    const float* ln_b   = (const float*)d_in[11];
    const float* out_w  = (const float*)d_in[12];
    const float* out_b  = (const float*)d_in[13];
    float* logits = (float*)d_out;

    float *x, *q, *k, *v, *ctx, *attn, *afrag, *wfrag;
    cudaGetSymbolAddress((void**)&x,     g_x);
    cudaGetSymbolAddress((void**)&q,     g_q);
    cudaGetSymbolAddress((void**)&k,     g_k);
    cudaGetSymbolAddress((void**)&v,     g_v);
    cudaGetSymbolAddress((void**)&ctx,   g_ctx);
    cudaGetSymbolAddress((void**)&attn,  g_attn);
    cudaGetSymbolAddress((void**)&afrag, g_afrag);
    cudaGetSymbolAddress((void**)&wfrag, g_wfrag);

    cudaFuncSetAttribute(gemm_mma,     cudaFuncAttributeMaxDynamicSharedMemorySize, GEMM_SMEM_BYTES);
    cudaFuncSetAttribute(gemm_mma_qkv, cudaFuncAttributeMaxDynamicSharedMemorySize, GEMM_SMEM_BYTES);
    cudaFuncSetAttribute(gemm_pre,     cudaFuncAttributeMaxDynamicSharedMemorySize, GEMM_SMEM_BYTES);

    // prelayout the logits weight once
    {
        dim3 gw(KC_D, NT_OUT);            // (32, 250)
        prelayout_W<<<gw, 256>>>(out_w, wfrag, VV);
    }

    embed_kernel<<<NROW, 256>>>(tokens, emb, x);

    dim3 gqkv(NROW / 128, DD / 128, 3);   // (16, 8, 3)
    dim3 gproj(NROW / 128, DD / 128);     // (16, 8)
    dim3 gattn(SS / 128, HH, BB);

    for (int l = 0; l < LL; l++) {
        size_t wo = (size_t)l * DD * DD;
        size_t bo = (size_t)l * DD;
        gemm_mma_qkv<<<gqkv, 256, GEMM_SMEM_BYTES>>>(x, qw + wo, kw + wo, vw + wo,
                                                     qb + bo, kb + bo, vb + bo, q, k, v);
        attn_kernel<<<gattn, 256>>>(q, k, v, ctx);
        gemm_mma<<<gproj, 256, GEMM_SMEM_BYTES>>>(ctx, ow + wo, ob + bo, attn, NROW, DD, DD);
        ln_res_kernel<<<NROW, 256>>>(x, attn, ln_g + bo, ln_b + bo);
    }

    // prelayout final activations, then fragment-major logits GEMM
    {
        dim3 ga(KC_D, MT_A);              // (32, 16)
        prelayout_A<<<ga, 256>>>(x, afrag, DD);
        dim3 gout(MT_A, NT_OUT);          // (16, 250)
        gemm_pre<<<gout, 256, GEMM_SMEM_BYTES>>>(afrag, wfrag, out_b, logits, VV, KC_D);
    }
}

// round 10
// speedup vs baseline: 1.1987x; 1.1987x over previous
#include <cuda_runtime.h>
#include <cstdint>
#include <math.h>

#define BB 2
#define SS 1024
#define DD 1024
#define HH 16
#define HD 64
#define LL 4
#define VV 32000
#define NROW (BB * SS)   // 2048
#define NT_OUT (VV / 128)   // 250 N-tiles for logits
#define MT_A   (NROW / 128) // 16 M-tiles
#define KC_D   (DD / 32)    // 32 K-chunks

// ---------------- scratch (static device globals; no allocs allowed) --------
__device__ float g_x[NROW * DD];
__device__ float g_q[NROW * DD];
__device__ float g_k[NROW * DD];
__device__ float g_v[NROW * DD];
__device__ float g_ctx[NROW * DD];
__device__ float g_attn[NROW * DD];
// fragment-major prelayout buffers
__device__ float g_afrag[MT_A * KC_D * 4096];          // 8 MB
__device__ float g_wfrag[(size_t)NT_OUT * KC_D * 4096];// 131 MB

__device__ __forceinline__ float tf32r(float x) {
    float r; asm("cvt.rna.tf32.f32 %0, %1;" : "=f"(r) : "f"(x)); return r;
}

// =================== tf32 mma.sync GEMM, fragment-major smem ================
// (per-layer kernel: CTA 128x128, BK=32, 2 stages, warp tile 64x32)

#define GEMM_SMEM_FLOATS 16384
#define GEMM_SMEM_BYTES  (GEMM_SMEM_FLOATS * 4)

__device__ __forceinline__ void gemm_core(
    const float* __restrict__ A, const float* __restrict__ W,
    const float* __restrict__ bias, float* __restrict__ C,
    int M, int N, int K, int bm, int bn, float* sm)
{
    const int t    = threadIdx.x;
    const int lane = t & 31;
    const int wid  = t >> 5;
    const int g    = lane >> 2;
    const int tg   = lane & 3;
    const int wm   = (wid & 1) * 64;
    const int wn   = (wid >> 1) * 32;

    float acc[4][4][4];
#pragma unroll
    for (int mf = 0; mf < 4; mf++)
#pragma unroll
        for (int nf = 0; nf < 4; nf++)
#pragma unroll
            for (int r = 0; r < 4; r++) acc[mf][nf][r] = 0.0f;

    int aBase[4], bBase[4];
#pragma unroll
    for (int i = 0; i < 4; i++) {
        int idx = t + i * 256;
        {
            int row = idx >> 3, c4 = idx & 7;
            int mi = row >> 4, m16 = row & 15;
            int ga = m16 & 7, rA = m16 >> 3;
            int ki = c4 >> 1, khi = c4 & 1;
            aBase[i] = ((mi * 4 + ki) * 32) * 4 + (rA + 2 * khi);
            aBase[i] |= (ga << 24) | (ki << 28);
        }
        {
            int rowk = idx >> 5, c4 = idx & 31;
            int n0 = c4 * 4;
            int ki = rowk >> 3, kk = rowk & 7;
            int tgb = kk & 3, hi = kk >> 2;
            int ni = n0 >> 3, g0 = n0 & 7;
            int swz = ((ni & 3) << 3) ^ (((ni >> 2) & 3) << 1);
            int ln0 = g0 * 4 + tgb;
            bBase[i] = ((ni * 4 + ki) * 32) * 2 + hi;
            bBase[i] |= (ln0 << 20) | (swz << 26);
        }
    }

    const int nkt = K >> 5;

    const float* aPtr[4];
    const float* bPtr[4];
#pragma unroll
    for (int i = 0; i < 4; i++) {
        int idx = t + i * 256;
        aPtr[i] = A + (size_t)(bm + (idx >> 3)) * K + (idx & 7) * 4;
        bPtr[i] = W + (size_t)(idx >> 5) * N + bn + (idx & 31) * 4;
    }

    auto storeA = [&](int s, int i, float4 v) {
        int meta = aBase[i];
        int base = meta & 0xFFFFF;
        int ga   = (meta >> 24) & 7;
        int ki   = (meta >> 28) & 3;
        float* dst = sm + s * 4096;
        float vv[4] = {tf32r(v.x), tf32r(v.y), tf32r(v.z), tf32r(v.w)};
#pragma unroll
        for (int e = 0; e < 4; e++) {
            int lp = (ga * 4 + e) ^ ki;
            dst[base + lp * 4] = vv[e];
        }
    };
    auto storeB = [&](int s, int i, float4 v) {
        int meta = bBase[i];
        int base = meta & 0xFFFFF;
        int ln0  = (meta >> 20) & 63;
        int swz  = (meta >> 26) & 31;
        float* dst = sm + 8192 + s * 4096;
        float vv[4] = {tf32r(v.x), tf32r(v.y), tf32r(v.z), tf32r(v.w)};
#pragma unroll
        for (int e = 0; e < 4; e++) {
            int lp = (ln0 + 4 * e) ^ swz;
            dst[base + lp * 2] = vv[e];
        }
    };

#pragma unroll
    for (int i = 0; i < 4; i++) {
        storeA(0, i, *(const float4*)aPtr[i]);
        storeB(0, i, *(const float4*)bPtr[i]);
    }
    __syncthreads();

    int bswz[4];
#pragma unroll
    for (int nf = 0; nf < 4; nf++) {
        int ni = (wid >> 1) * 4 + nf;
        bswz[nf] = lane ^ ((ni & 3) << 3) ^ (((ni >> 2) & 3) << 1);
    }

    for (int kt = 0; kt < nkt; kt++) {
        const int cur = kt & 1;
        float4 pa[4], pb[4];
        const bool pf = (kt + 1 < nkt);
        if (pf) {
            const size_t ko = (size_t)(kt + 1) << 5;
#pragma unroll
            for (int i = 0; i < 4; i++) {
                pa[i] = *(const float4*)(aPtr[i] + ko);
                pb[i] = *(const float4*)(bPtr[i] + ko * (size_t)N);
            }
        }

        const float* asb = sm + cur * 4096;
        const float* bsb = sm + 8192 + cur * 4096;
#pragma unroll
        for (int ki = 0; ki < 4; ki++) {
            float4 afv[4];
            float2 bfv[4];
#pragma unroll
            for (int mf = 0; mf < 4; mf++) {
                int mi = (wid & 1) * 4 + mf;
                afv[mf] = *(const float4*)(asb + ((mi * 4 + ki) * 32 + (lane ^ ki)) * 4);
            }
#pragma unroll
            for (int nf = 0; nf < 4; nf++) {
                int ni = (wid >> 1) * 4 + nf;
                bfv[nf] = *(const float2*)(bsb + ((ni * 4 + ki) * 32 + bswz[nf]) * 2);
            }
#pragma unroll
            for (int mf = 0; mf < 4; mf++)
#pragma unroll
                for (int nf = 0; nf < 4; nf++) {
                    asm volatile(
                        "mma.sync.aligned.m16n8k8.row.col.f32.tf32.tf32.f32 "
                        "{%0,%1,%2,%3}, {%4,%5,%6,%7}, {%8,%9}, {%0,%1,%2,%3};"
                        : "+f"(acc[mf][nf][0]), "+f"(acc[mf][nf][1]),
                          "+f"(acc[mf][nf][2]), "+f"(acc[mf][nf][3])
                        : "r"(__float_as_uint(afv[mf].x)), "r"(__float_as_uint(afv[mf].y)),
                          "r"(__float_as_uint(afv[mf].z)), "r"(__float_as_uint(afv[mf].w)),
                          "r"(__float_as_uint(bfv[nf].x)), "r"(__float_as_uint(bfv[nf].y)));
                }
        }

        if (pf) {
            const int nxt = 1 - cur;
#pragma unroll
            for (int i = 0; i < 4; i++) {
                storeA(nxt, i, pa[i]);
                storeB(nxt, i, pb[i]);
            }
        }
        __syncthreads();
    }

#pragma unroll
    for (int mf = 0; mf < 4; mf++) {
        const int r0 = bm + wm + mf * 16 + g;
        const int r1 = r0 + 8;
#pragma unroll
        for (int nf = 0; nf < 4; nf++) {
            const int col = bn + wn + nf * 8 + tg * 2;
            const float b0 = bias[col], b1 = bias[col + 1];
            float2 v0 = make_float2(acc[mf][nf][0] + b0, acc[mf][nf][1] + b1);
            float2 v1 = make_float2(acc[mf][nf][2] + b0, acc[mf][nf][3] + b1);
            *(float2*)(C + (size_t)r0 * N + col) = v0;
            *(float2*)(C + (size_t)r1 * N + col) = v1;
        }
    }
}

__global__ void __launch_bounds__(256)
gemm_mma(const float* __restrict__ A, const float* __restrict__ W,
         const float* __restrict__ bias, float* __restrict__ C,
         int M, int N, int K)
{
    extern __shared__ float sm[];
    gemm_core(A, W, bias, C, M, N, K, blockIdx.x * 128, blockIdx.y * 128, sm);
}

__global__ void __launch_bounds__(256)
gemm_mma_qkv(const float* __restrict__ A,
             const float* __restrict__ qw, const float* __restrict__ kw,
             const float* __restrict__ vw,
             const float* __restrict__ qb, const float* __restrict__ kb,
             const float* __restrict__ vb,
             float* __restrict__ qo, float* __restrict__ ko, float* __restrict__ vo)
{
    extern __shared__ float sm[];
    const float* W    = (blockIdx.z == 0) ? qw : (blockIdx.z == 1) ? kw : vw;
    const float* bias = (blockIdx.z == 0) ? qb : (blockIdx.z == 1) ? kb : vb;
    float*       C    = (blockIdx.z == 0) ? qo : (blockIdx.z == 1) ? ko : vo;
    gemm_core(A, W, bias, C, NROW, DD, DD, blockIdx.x * 128, blockIdx.y * 128, sm);
}

// =================== prelayout kernels (scatter ONCE into gmem) =============
__global__ void __launch_bounds__(256)
prelayout_A(const float* __restrict__ A, float* __restrict__ out, int K)
{
    const int kc = blockIdx.x;
    const int mt = blockIdx.y;
    const int t  = threadIdx.x;
    float* dst = out + ((size_t)mt * gridDim.x + kc) * 4096;
#pragma unroll
    for (int i = 0; i < 4; i++) {
        int idx = t + i * 256;
        int row = idx >> 3, c4 = idx & 7;
        int mi = row >> 4, m16 = row & 15;
        int ga = m16 & 7, rA = m16 >> 3;
        int ki = c4 >> 1, khi = c4 & 1;
        int base = ((mi * 4 + ki) * 32) * 4 + (rA + 2 * khi);
        float4 v = *(const float4*)(A + (size_t)(mt * 128 + row) * K + kc * 32 + c4 * 4);
        float vv[4] = {tf32r(v.x), tf32r(v.y), tf32r(v.z), tf32r(v.w)};
#pragma unroll
        for (int e = 0; e < 4; e++) {
            int lp = (ga * 4 + e) ^ ki;
            dst[base + lp * 4] = vv[e];
        }
    }
}

__global__ void __launch_bounds__(256)
prelayout_W(const float* __restrict__ W, float* __restrict__ out, int N)
{
    const int kc = blockIdx.x;
    const int nt = blockIdx.y;
    const int t  = threadIdx.x;
    float* dst = out + ((size_t)nt * gridDim.x + kc) * 4096;
#pragma unroll
    for (int i = 0; i < 4; i++) {
        int idx = t + i * 256;
        int rowk = idx >> 5, c4 = idx & 31;
        int n0 = c4 * 4;
        int ki = rowk >> 3, kk = rowk & 7;
        int tgb = kk & 3, hi = kk >> 2;
        int ni = n0 >> 3, g0 = n0 & 7;
        int swz = ((ni & 3) << 3) ^ (((ni >> 2) & 3) << 1);
        int ln0 = g0 * 4 + tgb;
        int base = ((ni * 4 + ki) * 32) * 2 + hi;
        float4 v = *(const float4*)(W + (size_t)(kc * 32 + rowk) * N + nt * 128 + n0);
        float vv[4] = {tf32r(v.x), tf32r(v.y), tf32r(v.z), tf32r(v.w)};
#pragma unroll
        for (int e = 0; e < 4; e++) {
            int lp = (ln0 + 4 * e) ^ swz;
            dst[base + lp * 2] = vv[e];
        }
    }
}

// =================== GEMM on prelaid fragment-major operands ================
__global__ void __launch_bounds__(256)
gemm_pre(const float* __restrict__ afrag, const float* __restrict__ wfrag,
         const float* __restrict__ bias, float* __restrict__ C,
         int N, int nkc)
{
    extern __shared__ float sm[];
    const int t    = threadIdx.x;
    const int lane = t & 31;
    const int wid  = t >> 5;
    const int g    = lane >> 2;
    const int tg   = lane & 3;
    const int mt   = blockIdx.x;
    const int nt   = blockIdx.y;
    const int wm   = (wid & 1) * 64;
    const int wn   = (wid >> 1) * 32;

    float acc[4][4][4];
#pragma unroll
    for (int mf = 0; mf < 4; mf++)
#pragma unroll
        for (int nf = 0; nf < 4; nf++)
#pragma unroll
            for (int r = 0; r < 4; r++) acc[mf][nf][r] = 0.0f;

    const float* aSrc = afrag + (size_t)mt * nkc * 4096;
    const float* bSrc = wfrag + (size_t)nt * nkc * 4096;

#pragma unroll
    for (int i = 0; i < 4; i++) {
        int o4 = (t + i * 256) * 4;
        *(float4*)(sm + o4)        = *(const float4*)(aSrc + o4);
        *(float4*)(sm + 8192 + o4) = *(const float4*)(bSrc + o4);
    }
    __syncthreads();

    int bswz[4];
#pragma unroll
    for (int nf = 0; nf < 4; nf++) {
        int ni = (wid >> 1) * 4 + nf;
        bswz[nf] = lane ^ ((ni & 3) << 3) ^ (((ni >> 2) & 3) << 1);
    }

    for (int kt = 0; kt < nkc; kt++) {
        const int cur = kt & 1;
        float4 pa[4], pb[4];
        const bool pf = (kt + 1 < nkc);
        if (pf) {
            const float* an = aSrc + (size_t)(kt + 1) * 4096;
            const float* bn = bSrc + (size_t)(kt + 1) * 4096;
#pragma unroll
            for (int i = 0; i < 4; i++) {
                int o4 = (t + i * 256) * 4;
                pa[i] = *(const float4*)(an + o4);
                pb[i] = *(const float4*)(bn + o4);
            }
        }

        const float* asb = sm + cur * 4096;
        const float* bsb = sm + 8192 + cur * 4096;
#pragma unroll
        for (int ki = 0; ki < 4; ki++) {
            float4 afv[4];
            float2 bfv[4];
#pragma unroll
            for (int mf = 0; mf < 4; mf++) {
                int mi = (wid & 1) * 4 + mf;
                afv[mf] = *(const float4*)(asb + ((mi * 4 + ki) * 32 + (lane ^ ki)) * 4);
            }
#pragma unroll
            for (int nf = 0; nf < 4; nf++) {
                int ni = (wid >> 1) * 4 + nf;
                bfv[nf] = *(const float2*)(bsb + ((ni * 4 + ki) * 32 + bswz[nf]) * 2);
            }
#pragma unroll
            for (int mf = 0; mf < 4; mf++)
#pragma unroll
                for (int nf = 0; nf < 4; nf++) {
                    asm volatile(
                        "mma.sync.aligned.m16n8k8.row.col.f32.tf32.tf32.f32 "
                        "{%0,%1,%2,%3}, {%4,%5,%6,%7}, {%8,%9}, {%0,%1,%2,%3};"
                        : "+f"(acc[mf][nf][0]), "+f"(acc[mf][nf][1]),
                          "+f"(acc[mf][nf][2]), "+f"(acc[mf][nf][3])
                        : "r"(__float_as_uint(afv[mf].x)), "r"(__float_as_uint(afv[mf].y)),
                          "r"(__float_as_uint(afv[mf].z)), "r"(__float_as_uint(afv[mf].w)),
                          "r"(__float_as_uint(bfv[nf].x)), "r"(__float_as_uint(bfv[nf].y)));
                }
        }

        if (pf) {
            const int nxt = 1 - cur;
#pragma unroll
            for (int i = 0; i < 4; i++) {
                int o4 = (t + i * 256) * 4;
                *(float4*)(sm + nxt * 4096 + o4)        = pa[i];
                *(float4*)(sm + 8192 + nxt * 4096 + o4) = pb[i];
            }
        }
        __syncthreads();
    }

#pragma unroll
    for (int mf = 0; mf < 4; mf++) {
        const int r0 = mt * 128 + wm + mf * 16 + g;
        const int r1 = r0 + 8;
#pragma unroll
        for (int nf = 0; nf < 4; nf++) {
            const int col = nt * 128 + wn + nf * 8 + tg * 2;
            const float b0 = bias[col], b1 = bias[col + 1];
            float2 v0 = make_float2(acc[mf][nf][0] + b0, acc[mf][nf][1] + b1);
            float2 v1 = make_float2(acc[mf][nf][2] + b0, acc[mf][nf][3] + b1);
            *(float2*)(C + (size_t)r0 * N + col) = v0;
            *(float2*)(C + (size_t)r1 * N + col) = v1;
        }
    }
}

// ---------------- embedding + sinusoidal positional encoding ---------------
__global__ void embed_kernel(const int* __restrict__ tokens,
                             const float* __restrict__ emb,
                             float* __restrict__ x)
{
    int row = blockIdx.x;
    int pos = row & (SS - 1);
    int tok = tokens[row];
    const float* e = emb + (size_t)tok * DD;
    float* xr = x + (size_t)row * DD;
    const float c = -logf(10000.0f) / (float)DD;
    for (int d = threadIdx.x; d < DD; d += blockDim.x) {
        int i = d >> 1;
        float ang = (float)pos * expf((float)(2 * i) * c);
        float pe = (d & 1) ? cosf(ang) : sinf(ang);
        xr[d] = e[d] + pe;
    }
}

// ---------------- causal flash attention, vectorized smem reads ------------
// grid: (S/128, H, B); 128 threads; thread = one query row.
// Ks/Vs consumed as float4 (LDS.128, warp-broadcast). 4-way split dot chains.
__global__ void __launch_bounds__(128)
attn_kernel(const float* __restrict__ Q, const float* __restrict__ K,
            const float* __restrict__ V, float* __restrict__ O)
{
    __shared__ __align__(16) float Ks[32][64];
    __shared__ __align__(16) float Vs[32][64];

    const int b = blockIdx.z;
    const int h = blockIdx.y;
    const int qi = blockIdx.x * 128 + threadIdx.x;
    const size_t base = (size_t)(b * SS) * DD + (size_t)h * HD;

    float q[64];
    {
        const float* qrow = Q + base + (size_t)qi * DD;
#pragma unroll
        for (int d = 0; d < 64; d += 4) {
            float4 v = *(const float4*)(qrow + d);
            q[d] = v.x; q[d+1] = v.y; q[d+2] = v.z; q[d+3] = v.w;
        }
    }

    float o[64];
#pragma unroll
    for (int d = 0; d < 64; d++) o[d] = 0.0f;
    float m = -1e30f, l = 0.0f;

    const int kend = blockIdx.x * 128 + 128;
    for (int kt = 0; kt < kend; kt += 32) {
#pragma unroll
        for (int i = 0; i < 4; i++) {
            int idx4 = threadIdx.x + i * 128;
            int r = idx4 >> 4;
            int c = (idx4 & 15) * 4;
            size_t gaddr = base + (size_t)(kt + r) * DD + c;
            *(float4*)&Ks[r][c] = *(const float4*)(K + gaddr);
            *(float4*)&Vs[r][c] = *(const float4*)(V + gaddr);
        }
        __syncthreads();

        const int jmax = qi - kt + 1;
        float sv[32];
        float tmax = -1e30f;
        // pass 1: scores, float4 smem reads + 4 independent FFMA chains
#pragma unroll
        for (int j = 0; j < 32; j++) {
            float s0 = 0.f, s1 = 0.f, s2 = 0.f, s3 = 0.f;
            const float4* krow = (const float4*)&Ks[j][0];
#pragma unroll
            for (int d4 = 0; d4 < 16; d4++) {
                float4 kv = krow[d4];
                s0 += q[d4 * 4 + 0] * kv.x;
                s1 += q[d4 * 4 + 1] * kv.y;
                s2 += q[d4 * 4 + 2] * kv.z;
                s3 += q[d4 * 4 + 3] * kv.w;
            }
            float s = ((s0 + s1) + (s2 + s3)) * 0.125f;
            sv[j] = (j < jmax) ? s : -1e30f;
            tmax = fmaxf(tmax, sv[j]);
        }
        float nm = fmaxf(m, tmax);
        float corr = __expf(m - nm);
        l *= corr;
#pragma unroll
        for (int d = 0; d < 64; d++) o[d] *= corr;
        // pass 2: accumulate PV with float4 smem reads
#pragma unroll
        for (int j = 0; j < 32; j++) {
            float p = __expf(sv[j] - nm);
            l += p;
            const float4* vrow = (const float4*)&Vs[j][0];
#pragma unroll
            for (int d4 = 0; d4 < 16; d4++) {
                float4 vv = vrow[d4];
                o[d4 * 4 + 0] += p * vv.x;
                o[d4 * 4 + 1] += p * vv.y;
                o[d4 * 4 + 2] += p * vv.z;
                o[d4 * 4 + 3] += p * vv.w;
            }
        }
        m = nm;
        __syncthreads();
    }

    float inv = 1.0f / l;
    float* orow = O + base + (size_t)qi * DD;
#pragma unroll
    for (int d = 0; d < 64; d += 4) {
        float4 v;
        v.x = o[d] * inv; v.y = o[d+1] * inv;
        v.z = o[d+2] * inv; v.w = o[d+3] * inv;
        *(float4*)(orow + d) = v;
    }
}

// ---------------- residual add + layernorm (in place on x) ----------------
__global__ void __launch_bounds__(256)
ln_res_kernel(float* __restrict__ x, const float* __restrict__ res,
              const float* __restrict__ g, const float* __restrict__ beta)
{
    __shared__ float red[256];
    const int row = blockIdx.x;
    const int tid = threadIdx.x;
    float* xr = x + (size_t)row * DD;
    const float* rr = res + (size_t)row * DD;

    float y[4];
    float s = 0.0f;
#pragma unroll
    for (int i = 0; i < 4; i++) {
        int d = tid + i * 256;
        y[i] = xr[d] + rr[d];
        s += y[i];
    }
    red[tid] = s; __syncthreads();
    for (int off = 128; off > 0; off >>= 1) {
        if (tid < off) red[tid] += red[tid + off];
        __syncthreads();
    }
    float mu = red[0] * (1.0f / (float)DD);
    __syncthreads();

    float vs = 0.0f;
#pragma unroll
    for (int i = 0; i < 4; i++) {
        float d2 = y[i] - mu;
        vs += d2 * d2;
    }
    red[tid] = vs; __syncthreads();
    for (int off = 128; off > 0; off >>= 1) {
        if (tid < off) red[tid] += red[tid + off];
        __syncthreads();
    }
    float var = red[0] * (1.0f / (float)DD);
    float inv = rsqrtf(var + 1e-5f);

#pragma unroll
    for (int i = 0; i < 4; i++) {
        int d = tid + i * 256;
        xr[d] = (y[i] - mu) * inv * g[d] + beta[d];
    }
}

// ---------------------------------------------------------------------------
extern "C" void kernel_launch(void* const* d_in, const int* in_sizes, int n_in,
                              void* d_out, int out_size)
{
    const int*   tokens = (const int*)  d_in[0];
    const float* emb    = (const float*)d_in[1];
    const float* qw     = (const float*)d_in[2];
    const float* qb     = (const float*)d_in[3];
    const float* kw     = (const float*)d_in[4];
    const float* kb     = (const float*)d_in[5];
    const float* vw     = (const float*)d_in[6];
    const float* vb     = (const float*)d_in[7];
    const float* ow     = (const float*)d_in[8];
    const float* ob     = (const float*)d_in[9];
    const float* ln_g   = (const float*)d_in[10];
    const float* ln_b   = (const float*)d_in[11];
    const float* out_w  = (const float*)d_in[12];
    const float* out_b  = (const float*)d_in[13];
    float* logits = (float*)d_out;

    float *x, *q, *k, *v, *ctx, *attn, *afrag, *wfrag;
    cudaGetSymbolAddress((void**)&x,     g_x);
    cudaGetSymbolAddress((void**)&q,     g_q);
    cudaGetSymbolAddress((void**)&k,     g_k);
    cudaGetSymbolAddress((void**)&v,     g_v);
    cudaGetSymbolAddress((void**)&ctx,   g_ctx);
    cudaGetSymbolAddress((void**)&attn,  g_attn);
    cudaGetSymbolAddress((void**)&afrag, g_afrag);
    cudaGetSymbolAddress((void**)&wfrag, g_wfrag);

    cudaFuncSetAttribute(gemm_mma,     cudaFuncAttributeMaxDynamicSharedMemorySize, GEMM_SMEM_BYTES);
    cudaFuncSetAttribute(gemm_mma_qkv, cudaFuncAttributeMaxDynamicSharedMemorySize, GEMM_SMEM_BYTES);
    cudaFuncSetAttribute(gemm_pre,     cudaFuncAttributeMaxDynamicSharedMemorySize, GEMM_SMEM_BYTES);

    // prelayout the logits weight once
    {
        dim3 gw(KC_D, NT_OUT);            // (32, 250)
        prelayout_W<<<gw, 256>>>(out_w, wfrag, VV);
    }

    embed_kernel<<<NROW, 256>>>(tokens, emb, x);

    dim3 gqkv(NROW / 128, DD / 128, 3);   // (16, 8, 3)
    dim3 gproj(NROW / 128, DD / 128);     // (16, 8)
    dim3 gattn(SS / 128, HH, BB);

    for (int l = 0; l < LL; l++) {
        size_t wo = (size_t)l * DD * DD;
        size_t bo = (size_t)l * DD;
        gemm_mma_qkv<<<gqkv, 256, GEMM_SMEM_BYTES>>>(x, qw + wo, kw + wo, vw + wo,
                                                     qb + bo, kb + bo, vb + bo, q, k, v);
        attn_kernel<<<gattn, 128>>>(q, k, v, ctx);
        gemm_mma<<<gproj, 256, GEMM_SMEM_BYTES>>>(ctx, ow + wo, ob + bo, attn, NROW, DD, DD);
        ln_res_kernel<<<NROW, 256>>>(x, attn, ln_g + bo, ln_b + bo);
    }

    // prelayout final activations, then fragment-major logits GEMM
    {
        dim3 ga(KC_D, MT_A);              // (32, 16)
        prelayout_A<<<ga, 256>>>(x, afrag, DD);
        dim3 gout(MT_A, NT_OUT);          // (16, 250)
        gemm_pre<<<gout, 256, GEMM_SMEM_BYTES>>>(afrag, wfrag, out_b, logits, VV, KC_D);
    }
}

// round 11
// speedup vs baseline: 1.7627x; 1.4705x over previous
#include <cuda_runtime.h>
#include <cstdint>
#include <math.h>

#define BB 2
#define SS 1024
#define DD 1024
#define HH 16
#define HD 64
#define LL 4
#define VV 32000
#define NROW (BB * SS)   // 2048
#define NT_OUT (VV / 128)   // 250 N-tiles for logits
#define MT_A   (NROW / 128) // 16 M-tiles
#define KC_D   (DD / 32)    // 32 K-chunks

// ---------------- scratch (static device globals; no allocs allowed) --------
__device__ float g_x[NROW * DD];
__device__ float g_q[NROW * DD];
__device__ float g_k[NROW * DD];
__device__ float g_v[NROW * DD];
__device__ float g_ctx[NROW * DD];
__device__ float g_attn[NROW * DD];
// fragment-major prelayout buffers
__device__ float g_afrag[MT_A * KC_D * 4096];          // 8 MB
__device__ float g_wfrag[(size_t)NT_OUT * KC_D * 4096];// 131 MB

__device__ __forceinline__ float tf32r(float x) {
    float r; asm("cvt.rna.tf32.f32 %0, %1;" : "=f"(r) : "f"(x)); return r;
}

__device__ __forceinline__ void mma16n8k8(float* d, const float* a, float bx, float by) {
    asm volatile(
        "mma.sync.aligned.m16n8k8.row.col.f32.tf32.tf32.f32 "
        "{%0,%1,%2,%3}, {%4,%5,%6,%7}, {%8,%9}, {%0,%1,%2,%3};"
        : "+f"(d[0]), "+f"(d[1]), "+f"(d[2]), "+f"(d[3])
        : "r"(__float_as_uint(a[0])), "r"(__float_as_uint(a[1])),
          "r"(__float_as_uint(a[2])), "r"(__float_as_uint(a[3])),
          "r"(__float_as_uint(bx)), "r"(__float_as_uint(by)));
}

// =================== tf32 mma.sync GEMM, fragment-major smem ================
// (per-layer kernel: CTA 128x128, BK=32, 2 stages, warp tile 64x32)

#define GEMM_SMEM_FLOATS 16384
#define GEMM_SMEM_BYTES  (GEMM_SMEM_FLOATS * 4)

__device__ __forceinline__ void gemm_core(
    const float* __restrict__ A, const float* __restrict__ W,
    const float* __restrict__ bias, float* __restrict__ C,
    int M, int N, int K, int bm, int bn, float* sm)
{
    const int t    = threadIdx.x;
    const int lane = t & 31;
    const int wid  = t >> 5;
    const int g    = lane >> 2;
    const int tg   = lane & 3;
    const int wm   = (wid & 1) * 64;
    const int wn   = (wid >> 1) * 32;

    float acc[4][4][4];
#pragma unroll
    for (int mf = 0; mf < 4; mf++)
#pragma unroll
        for (int nf = 0; nf < 4; nf++)
#pragma unroll
            for (int r = 0; r < 4; r++) acc[mf][nf][r] = 0.0f;

    int aBase[4], bBase[4];
#pragma unroll
    for (int i = 0; i < 4; i++) {
        int idx = t + i * 256;
        {
            int row = idx >> 3, c4 = idx & 7;
            int mi = row >> 4, m16 = row & 15;
            int ga = m16 & 7, rA = m16 >> 3;
            int ki = c4 >> 1, khi = c4 & 1;
            aBase[i] = ((mi * 4 + ki) * 32) * 4 + (rA + 2 * khi);
            aBase[i] |= (ga << 24) | (ki << 28);
        }
        {
            int rowk = idx >> 5, c4 = idx & 31;
            int n0 = c4 * 4;
            int ki = rowk >> 3, kk = rowk & 7;
            int tgb = kk & 3, hi = kk >> 2;
            int ni = n0 >> 3, g0 = n0 & 7;
            int swz = ((ni & 3) << 3) ^ (((ni >> 2) & 3) << 1);
            int ln0 = g0 * 4 + tgb;
            bBase[i] = ((ni * 4 + ki) * 32) * 2 + hi;
            bBase[i] |= (ln0 << 20) | (swz << 26);
        }
    }

    const int nkt = K >> 5;

    const float* aPtr[4];
    const float* bPtr[4];
#pragma unroll
    for (int i = 0; i < 4; i++) {
        int idx = t + i * 256;
        aPtr[i] = A + (size_t)(bm + (idx >> 3)) * K + (idx & 7) * 4;
        bPtr[i] = W + (size_t)(idx >> 5) * N + bn + (idx & 31) * 4;
    }

    auto storeA = [&](int s, int i, float4 v) {
        int meta = aBase[i];
        int base = meta & 0xFFFFF;
        int ga   = (meta >> 24) & 7;
        int ki   = (meta >> 28) & 3;
        float* dst = sm + s * 4096;
        float vv[4] = {tf32r(v.x), tf32r(v.y), tf32r(v.z), tf32r(v.w)};
#pragma unroll
        for (int e = 0; e < 4; e++) {
            int lp = (ga * 4 + e) ^ ki;
            dst[base + lp * 4] = vv[e];
        }
    };
    auto storeB = [&](int s, int i, float4 v) {
        int meta = bBase[i];
        int base = meta & 0xFFFFF;
        int ln0  = (meta >> 20) & 63;
        int swz  = (meta >> 26) & 31;
        float* dst = sm + 8192 + s * 4096;
        float vv[4] = {tf32r(v.x), tf32r(v.y), tf32r(v.z), tf32r(v.w)};
#pragma unroll
        for (int e = 0; e < 4; e++) {
            int lp = (ln0 + 4 * e) ^ swz;
            dst[base + lp * 2] = vv[e];
        }
    };

#pragma unroll
    for (int i = 0; i < 4; i++) {
        storeA(0, i, *(const float4*)aPtr[i]);
        storeB(0, i, *(const float4*)bPtr[i]);
    }
    __syncthreads();

    int bswz[4];
#pragma unroll
    for (int nf = 0; nf < 4; nf++) {
        int ni = (wid >> 1) * 4 + nf;
        bswz[nf] = lane ^ ((ni & 3) << 3) ^ (((ni >> 2) & 3) << 1);
    }

    for (int kt = 0; kt < nkt; kt++) {
        const int cur = kt & 1;
        float4 pa[4], pb[4];
        const bool pf = (kt + 1 < nkt);
        if (pf) {
            const size_t ko = (size_t)(kt + 1) << 5;
#pragma unroll
            for (int i = 0; i < 4; i++) {
                pa[i] = *(const float4*)(aPtr[i] + ko);
                pb[i] = *(const float4*)(bPtr[i] + ko * (size_t)N);
            }
        }

        const float* asb = sm + cur * 4096;
        const float* bsb = sm + 8192 + cur * 4096;
#pragma unroll
        for (int ki = 0; ki < 4; ki++) {
            float4 afv[4];
            float2 bfv[4];
#pragma unroll
            for (int mf = 0; mf < 4; mf++) {
                int mi = (wid & 1) * 4 + mf;
                afv[mf] = *(const float4*)(asb + ((mi * 4 + ki) * 32 + (lane ^ ki)) * 4);
            }
#pragma unroll
            for (int nf = 0; nf < 4; nf++) {
                int ni = (wid >> 1) * 4 + nf;
                bfv[nf] = *(const float2*)(bsb + ((ni * 4 + ki) * 32 + bswz[nf]) * 2);
            }
#pragma unroll
            for (int mf = 0; mf < 4; mf++)
#pragma unroll
                for (int nf = 0; nf < 4; nf++)
                    mma16n8k8(acc[mf][nf], (const float*)&afv[mf], bfv[nf].x, bfv[nf].y);
        }

        if (pf) {
            const int nxt = 1 - cur;
#pragma unroll
            for (int i = 0; i < 4; i++) {
                storeA(nxt, i, pa[i]);
                storeB(nxt, i, pb[i]);
            }
        }
        __syncthreads();
    }

#pragma unroll
    for (int mf = 0; mf < 4; mf++) {
        const int r0 = bm + wm + mf * 16 + g;
        const int r1 = r0 + 8;
#pragma unroll
        for (int nf = 0; nf < 4; nf++) {
            const int col = bn + wn + nf * 8 + tg * 2;
            const float b0 = bias[col], b1 = bias[col + 1];
            float2 v0 = make_float2(acc[mf][nf][0] + b0, acc[mf][nf][1] + b1);
            float2 v1 = make_float2(acc[mf][nf][2] + b0, acc[mf][nf][3] + b1);
            *(float2*)(C + (size_t)r0 * N + col) = v0;
            *(float2*)(C + (size_t)r1 * N + col) = v1;
        }
    }
}

__global__ void __launch_bounds__(256)
gemm_mma(const float* __restrict__ A, const float* __restrict__ W,
         const float* __restrict__ bias, float* __restrict__ C,
         int M, int N, int K)
{
    extern __shared__ float sm[];
    gemm_core(A, W, bias, C, M, N, K, blockIdx.x * 128, blockIdx.y * 128, sm);
}

__global__ void __launch_bounds__(256)
gemm_mma_qkv(const float* __restrict__ A,
             const float* __restrict__ qw, const float* __restrict__ kw,
             const float* __restrict__ vw,
             const float* __restrict__ qb, const float* __restrict__ kb,
             const float* __restrict__ vb,
             float* __restrict__ qo, float* __restrict__ ko, float* __restrict__ vo)
{
    extern __shared__ float sm[];
    const float* W    = (blockIdx.z == 0) ? qw : (blockIdx.z == 1) ? kw : vw;
    const float* bias = (blockIdx.z == 0) ? qb : (blockIdx.z == 1) ? kb : vb;
    float*       C    = (blockIdx.z == 0) ? qo : (blockIdx.z == 1) ? ko : vo;
    gemm_core(A, W, bias, C, NROW, DD, DD, blockIdx.x * 128, blockIdx.y * 128, sm);
}

// =================== prelayout kernels (scatter ONCE into gmem) =============
__global__ void __launch_bounds__(256)
prelayout_A(const float* __restrict__ A, float* __restrict__ out, int K)
{
    const int kc = blockIdx.x;
    const int mt = blockIdx.y;
    const int t  = threadIdx.x;
    float* dst = out + ((size_t)mt * gridDim.x + kc) * 4096;
#pragma unroll
    for (int i = 0; i < 4; i++) {
        int idx = t + i * 256;
        int row = idx >> 3, c4 = idx & 7;
        int mi = row >> 4, m16 = row & 15;
        int ga = m16 & 7, rA = m16 >> 3;
        int ki = c4 >> 1, khi = c4 & 1;
        int base = ((mi * 4 + ki) * 32) * 4 + (rA + 2 * khi);
        float4 v = *(const float4*)(A + (size_t)(mt * 128 + row) * K + kc * 32 + c4 * 4);
        float vv[4] = {tf32r(v.x), tf32r(v.y), tf32r(v.z), tf32r(v.w)};
#pragma unroll
        for (int e = 0; e < 4; e++) {
            int lp = (ga * 4 + e) ^ ki;
            dst[base + lp * 4] = vv[e];
        }
    }
}

__global__ void __launch_bounds__(256)
prelayout_W(const float* __restrict__ W, float* __restrict__ out, int N)
{
    const int kc = blockIdx.x;
    const int nt = blockIdx.y;
    const int t  = threadIdx.x;
    float* dst = out + ((size_t)nt * gridDim.x + kc) * 4096;
#pragma unroll
    for (int i = 0; i < 4; i++) {
        int idx = t + i * 256;
        int rowk = idx >> 5, c4 = idx & 31;
        int n0 = c4 * 4;
        int ki = rowk >> 3, kk = rowk & 7;
        int tgb = kk & 3, hi = kk >> 2;
        int ni = n0 >> 3, g0 = n0 & 7;
        int swz = ((ni & 3) << 3) ^ (((ni >> 2) & 3) << 1);
        int ln0 = g0 * 4 + tgb;
        int base = ((ni * 4 + ki) * 32) * 2 + hi;
        float4 v = *(const float4*)(W + (size_t)(kc * 32 + rowk) * N + nt * 128 + n0);
        float vv[4] = {tf32r(v.x), tf32r(v.y), tf32r(v.z), tf32r(v.w)};
#pragma unroll
        for (int e = 0; e < 4; e++) {
            int lp = (ln0 + 4 * e) ^ swz;
            dst[base + lp * 2] = vv[e];
        }
    }
}

// =================== GEMM on prelaid fragment-major operands ================
__global__ void __launch_bounds__(256)
gemm_pre(const float* __restrict__ afrag, const float* __restrict__ wfrag,
         const float* __restrict__ bias, float* __restrict__ C,
         int N, int nkc)
{
    extern __shared__ float sm[];
    const int t    = threadIdx.x;
    const int lane = t & 31;
    const int wid  = t >> 5;
    const int g    = lane >> 2;
    const int tg   = lane & 3;
    const int mt   = blockIdx.x;
    const int nt   = blockIdx.y;
    const int wm   = (wid & 1) * 64;
    const int wn   = (wid >> 1) * 32;

    float acc[4][4][4];
#pragma unroll
    for (int mf = 0; mf < 4; mf++)
#pragma unroll
        for (int nf = 0; nf < 4; nf++)
#pragma unroll
            for (int r = 0; r < 4; r++) acc[mf][nf][r] = 0.0f;

    const float* aSrc = afrag + (size_t)mt * nkc * 4096;
    const float* bSrc = wfrag + (size_t)nt * nkc * 4096;

#pragma unroll
    for (int i = 0; i < 4; i++) {
        int o4 = (t + i * 256) * 4;
        *(float4*)(sm + o4)        = *(const float4*)(aSrc + o4);
        *(float4*)(sm + 8192 + o4) = *(const float4*)(bSrc + o4);
    }
    __syncthreads();

    int bswz[4];
#pragma unroll
    for (int nf = 0; nf < 4; nf++) {
        int ni = (wid >> 1) * 4 + nf;
        bswz[nf] = lane ^ ((ni & 3) << 3) ^ (((ni >> 2) & 3) << 1);
    }

    for (int kt = 0; kt < nkc; kt++) {
        const int cur = kt & 1;
        float4 pa[4], pb[4];
        const bool pf = (kt + 1 < nkc);
        if (pf) {
            const float* an = aSrc + (size_t)(kt + 1) * 4096;
            const float* bn = bSrc + (size_t)(kt + 1) * 4096;
#pragma unroll
            for (int i = 0; i < 4; i++) {
                int o4 = (t + i * 256) * 4;
                pa[i] = *(const float4*)(an + o4);
                pb[i] = *(const float4*)(bn + o4);
            }
        }

        const float* asb = sm + cur * 4096;
        const float* bsb = sm + 8192 + cur * 4096;
#pragma unroll
        for (int ki = 0; ki < 4; ki++) {
            float4 afv[4];
            float2 bfv[4];
#pragma unroll
            for (int mf = 0; mf < 4; mf++) {
                int mi = (wid & 1) * 4 + mf;
                afv[mf] = *(const float4*)(asb + ((mi * 4 + ki) * 32 + (lane ^ ki)) * 4);
            }
#pragma unroll
            for (int nf = 0; nf < 4; nf++) {
                int ni = (wid >> 1) * 4 + nf;
                bfv[nf] = *(const float2*)(bsb + ((ni * 4 + ki) * 32 + bswz[nf]) * 2);
            }
#pragma unroll
            for (int mf = 0; mf < 4; mf++)
#pragma unroll
                for (int nf = 0; nf < 4; nf++)
                    mma16n8k8(acc[mf][nf], (const float*)&afv[mf], bfv[nf].x, bfv[nf].y);
        }

        if (pf) {
            const int nxt = 1 - cur;
#pragma unroll
            for (int i = 0; i < 4; i++) {
                int o4 = (t + i * 256) * 4;
                *(float4*)(sm + nxt * 4096 + o4)        = pa[i];
                *(float4*)(sm + 8192 + nxt * 4096 + o4) = pb[i];
            }
        }
        __syncthreads();
    }

#pragma unroll
    for (int mf = 0; mf < 4; mf++) {
        const int r0 = mt * 128 + wm + mf * 16 + g;
        const int r1 = r0 + 8;
#pragma unroll
        for (int nf = 0; nf < 4; nf++) {
            const int col = nt * 128 + wn + nf * 8 + tg * 2;
            const float b0 = bias[col], b1 = bias[col + 1];
            float2 v0 = make_float2(acc[mf][nf][0] + b0, acc[mf][nf][1] + b1);
            float2 v1 = make_float2(acc[mf][nf][2] + b0, acc[mf][nf][3] + b1);
            *(float2*)(C + (size_t)r0 * N + col) = v0;
            *(float2*)(C + (size_t)r1 * N + col) = v1;
        }
    }
}

// ---------------- embedding + sinusoidal positional encoding ---------------
__global__ void embed_kernel(const int* __restrict__ tokens,
                             const float* __restrict__ emb,
                             float* __restrict__ x)
{
    int row = blockIdx.x;
    int pos = row & (SS - 1);
    int tok = tokens[row];
    const float* e = emb + (size_t)tok * DD;
    float* xr = x + (size_t)row * DD;
    const float c = -logf(10000.0f) / (float)DD;
    for (int d = threadIdx.x; d < DD; d += blockDim.x) {
        int i = d >> 1;
        float ang = (float)pos * expf((float)(2 * i) * c);
        float pe = (d & 1) ? cosf(ang) : sinf(ang);
        xr[d] = e[d] + pe;
    }
}

// ============= tensor-core causal flash attention (tf32 mma) ================
// grid (S/128, H, B); 128 threads = 4 warps; warp owns 32 query rows.
// Per 32-key tile: S = Q.K^T via m16n8k8 (Q as A-frags in regs, K in padded
// smem), fragment-level causal mask + online softmax, P -> per-warp smem,
// O += P.V via m16n8k8.
__global__ void __launch_bounds__(128)
attn_mma_kernel(const float* __restrict__ Q, const float* __restrict__ K,
                const float* __restrict__ V, float* __restrict__ O)
{
    __shared__ __align__(16) float Ks[32][68];   // bank: 4g+tg  -> conflict-free B reads
    __shared__ __align__(16) float Vs[32][72];   // bank: 8tg+g  -> conflict-free B reads
    __shared__ __align__(16) float Ps[4][32][36];// bank: 4g+tg  -> conflict-free A reads

    const int b  = blockIdx.z;
    const int h  = blockIdx.y;
    const int qb = blockIdx.x * 128;
    const int tid = threadIdx.x;
    const int w    = tid >> 5;
    const int lane = tid & 31;
    const int g    = lane >> 2;
    const int tg   = lane & 3;
    const size_t base = (size_t)(b * SS) * DD + (size_t)h * HD;

    // ---- Q as A-fragments (scaled by 1/sqrt(64), tf32-rounded) ----
    float qf[2][8][4];
#pragma unroll
    for (int mf = 0; mf < 2; mf++) {
        const int r0 = qb + w * 32 + mf * 16 + g;
        const int r1 = r0 + 8;
#pragma unroll
        for (int k8 = 0; k8 < 8; k8++) {
            int k0 = k8 * 8;
            qf[mf][k8][0] = tf32r(Q[base + (size_t)r0 * DD + k0 + tg]     * 0.125f);
            qf[mf][k8][1] = tf32r(Q[base + (size_t)r1 * DD + k0 + tg]     * 0.125f);
            qf[mf][k8][2] = tf32r(Q[base + (size_t)r0 * DD + k0 + tg + 4] * 0.125f);
            qf[mf][k8][3] = tf32r(Q[base + (size_t)r1 * DD + k0 + tg + 4] * 0.125f);
        }
    }

    float oacc[2][8][4];
#pragma unroll
    for (int mf = 0; mf < 2; mf++)
#pragma unroll
        for (int nf = 0; nf < 8; nf++)
#pragma unroll
            for (int r = 0; r < 4; r++) oacc[mf][nf][r] = 0.0f;
    float mrow[2][2], lrow[2][2];
#pragma unroll
    for (int mf = 0; mf < 2; mf++) {
        mrow[mf][0] = -1e30f; mrow[mf][1] = -1e30f;
        lrow[mf][0] = 0.0f;   lrow[mf][1] = 0.0f;
    }

    const int qmax_w = qb + w * 32 + 31;
    const int kend = qb + 128;
    for (int kt = 0; kt < kend; kt += 32) {
        // cooperative K/V tile load (tf32-rounded)
#pragma unroll
        for (int i = 0; i < 4; i++) {
            int idx4 = tid + i * 128;
            int r = idx4 >> 4;
            int c = (idx4 & 15) * 4;
            size_t ga = base + (size_t)(kt + r) * DD + c;
            float4 kv = *(const float4*)(K + ga);
            float4 vv = *(const float4*)(V + ga);
            Ks[r][c]   = tf32r(kv.x); Ks[r][c+1] = tf32r(kv.y);
            Ks[r][c+2] = tf32r(kv.z); Ks[r][c+3] = tf32r(kv.w);
            Vs[r][c]   = tf32r(vv.x); Vs[r][c+1] = tf32r(vv.y);
            Vs[r][c+2] = tf32r(vv.z); Vs[r][c+3] = tf32r(vv.w);
        }
        __syncthreads();

        if (kt <= qmax_w) {   // warp-uniform: skip fully masked tiles
            // ---- S = Q . K^T ----
            float sacc[2][4][4];
#pragma unroll
            for (int mf = 0; mf < 2; mf++)
#pragma unroll
                for (int nf = 0; nf < 4; nf++)
#pragma unroll
                    for (int r = 0; r < 4; r++) sacc[mf][nf][r] = 0.0f;
#pragma unroll
            for (int k8 = 0; k8 < 8; k8++) {
                float2 bf[4];
#pragma unroll
                for (int nf = 0; nf < 4; nf++) {
                    bf[nf].x = Ks[nf * 8 + g][k8 * 8 + tg];
                    bf[nf].y = Ks[nf * 8 + g][k8 * 8 + tg + 4];
                }
#pragma unroll
                for (int mf = 0; mf < 2; mf++)
#pragma unroll
                    for (int nf = 0; nf < 4; nf++)
                        mma16n8k8(sacc[mf][nf], qf[mf][k8], bf[nf].x, bf[nf].y);
            }

            // ---- mask + online softmax + P store ----
#pragma unroll
            for (int mf = 0; mf < 2; mf++) {
                const int row0 = qb + w * 32 + mf * 16 + g;
                const int row1 = row0 + 8;
#pragma unroll
                for (int nf = 0; nf < 4; nf++) {
#pragma unroll
                    for (int e = 0; e < 2; e++) {
                        int key = kt + nf * 8 + tg * 2 + e;
                        if (key > row0) sacc[mf][nf][e]     = -1e30f;
                        if (key > row1) sacc[mf][nf][2 + e] = -1e30f;
                    }
                }
                float t0 = -1e30f, t1 = -1e30f;
#pragma unroll
                for (int nf = 0; nf < 4; nf++) {
                    t0 = fmaxf(t0, fmaxf(sacc[mf][nf][0], sacc[mf][nf][1]));
                    t1 = fmaxf(t1, fmaxf(sacc[mf][nf][2], sacc[mf][nf][3]));
                }
                t0 = fmaxf(t0, __shfl_xor_sync(0xFFFFFFFFu, t0, 1));
                t0 = fmaxf(t0, __shfl_xor_sync(0xFFFFFFFFu, t0, 2));
                t1 = fmaxf(t1, __shfl_xor_sync(0xFFFFFFFFu, t1, 1));
                t1 = fmaxf(t1, __shfl_xor_sync(0xFFFFFFFFu, t1, 2));
                float nm0 = fmaxf(mrow[mf][0], t0);
                float nm1 = fmaxf(mrow[mf][1], t1);
                float c0 = __expf(mrow[mf][0] - nm0);
                float c1 = __expf(mrow[mf][1] - nm1);
                mrow[mf][0] = nm0; mrow[mf][1] = nm1;

                float ps0 = 0.0f, ps1 = 0.0f;
#pragma unroll
                for (int nf = 0; nf < 4; nf++) {
#pragma unroll
                    for (int e = 0; e < 2; e++) {
                        float p0 = __expf(sacc[mf][nf][e]     - nm0);
                        float p1 = __expf(sacc[mf][nf][2 + e] - nm1);
                        sacc[mf][nf][e]     = p0;
                        sacc[mf][nf][2 + e] = p1;
                        ps0 += p0; ps1 += p1;
                    }
                }
                ps0 += __shfl_xor_sync(0xFFFFFFFFu, ps0, 1);
                ps0 += __shfl_xor_sync(0xFFFFFFFFu, ps0, 2);
                ps1 += __shfl_xor_sync(0xFFFFFFFFu, ps1, 1);
                ps1 += __shfl_xor_sync(0xFFFFFFFFu, ps1, 2);
                lrow[mf][0] = lrow[mf][0] * c0 + ps0;
                lrow[mf][1] = lrow[mf][1] * c1 + ps1;

#pragma unroll
                for (int nf2 = 0; nf2 < 8; nf2++) {
                    oacc[mf][nf2][0] *= c0; oacc[mf][nf2][1] *= c0;
                    oacc[mf][nf2][2] *= c1; oacc[mf][nf2][3] *= c1;
                }
#pragma unroll
                for (int nf = 0; nf < 4; nf++) {
                    float2 lo = make_float2(tf32r(sacc[mf][nf][0]), tf32r(sacc[mf][nf][1]));
                    float2 hi = make_float2(tf32r(sacc[mf][nf][2]), tf32r(sacc[mf][nf][3]));
                    *(float2*)&Ps[w][mf * 16 + g][nf * 8 + tg * 2]     = lo;
                    *(float2*)&Ps[w][mf * 16 + g + 8][nf * 8 + tg * 2] = hi;
                }
            }
            __syncwarp();

            // ---- O += P . V ----
#pragma unroll
            for (int kk = 0; kk < 4; kk++) {
                float af[2][4];
#pragma unroll
                for (int mf = 0; mf < 2; mf++) {
                    af[mf][0] = Ps[w][mf * 16 + g][kk * 8 + tg];
                    af[mf][1] = Ps[w][mf * 16 + g + 8][kk * 8 + tg];
                    af[mf][2] = Ps[w][mf * 16 + g][kk * 8 + tg + 4];
                    af[mf][3] = Ps[w][mf * 16 + g + 8][kk * 8 + tg + 4];
                }
#pragma unroll
                for (int nf2 = 0; nf2 < 8; nf2++) {
                    float bx = Vs[kk * 8 + tg][nf2 * 8 + g];
                    float by = Vs[kk * 8 + tg + 4][nf2 * 8 + g];
#pragma unroll
                    for (int mf = 0; mf < 2; mf++)
                        mma16n8k8(oacc[mf][nf2], af[mf], bx, by);
                }
            }
        }
        __syncthreads();
    }

    // ---- epilogue: normalize + store ----
#pragma unroll
    for (int mf = 0; mf < 2; mf++) {
        const int row0 = qb + w * 32 + mf * 16 + g;
        const int row1 = row0 + 8;
        const float inv0 = 1.0f / lrow[mf][0];
        const float inv1 = 1.0f / lrow[mf][1];
#pragma unroll
        for (int nf2 = 0; nf2 < 8; nf2++) {
            const int col = nf2 * 8 + tg * 2;
            float2 v0 = make_float2(oacc[mf][nf2][0] * inv0, oacc[mf][nf2][1] * inv0);
            float2 v1 = make_float2(oacc[mf][nf2][2] * inv1, oacc[mf][nf2][3] * inv1);
            *(float2*)(O + base + (size_t)row0 * DD + col) = v0;
            *(float2*)(O + base + (size_t)row1 * DD + col) = v1;
        }
    }
}

// ---------------- residual add + layernorm (in place on x) ----------------
__global__ void __launch_bounds__(256)
ln_res_kernel(float* __restrict__ x, const float* __restrict__ res,
              const float* __restrict__ g, const float* __restrict__ beta)
{
    __shared__ float red[256];
    const int row = blockIdx.x;
    const int tid = threadIdx.x;
    float* xr = x + (size_t)row * DD;
    const float* rr = res + (size_t)row * DD;

    float y[4];
    float s = 0.0f;
#pragma unroll
    for (int i = 0; i < 4; i++) {
        int d = tid + i * 256;
        y[i] = xr[d] + rr[d];
        s += y[i];
    }
    red[tid] = s; __syncthreads();
    for (int off = 128; off > 0; off >>= 1) {
        if (tid < off) red[tid] += red[tid + off];
        __syncthreads();
    }
    float mu = red[0] * (1.0f / (float)DD);
    __syncthreads();

    float vs = 0.0f;
#pragma unroll
    for (int i = 0; i < 4; i++) {
        float d2 = y[i] - mu;
        vs += d2 * d2;
    }
    red[tid] = vs; __syncthreads();
    for (int off = 128; off > 0; off >>= 1) {
        if (tid < off) red[tid] += red[tid + off];
        __syncthreads();
    }
    float var = red[0] * (1.0f / (float)DD);
    float inv = rsqrtf(var + 1e-5f);

#pragma unroll
    for (int i = 0; i < 4; i++) {
        int d = tid + i * 256;
        xr[d] = (y[i] - mu) * inv * g[d] + beta[d];
    }
}

// ---------------------------------------------------------------------------
extern "C" void kernel_launch(void* const* d_in, const int* in_sizes, int n_in,
                              void* d_out, int out_size)
{
    const int*   tokens = (const int*)  d_in[0];
    const float* emb    = (const float*)d_in[1];
    const float* qw     = (const float*)d_in[2];
    const float* qb     = (const float*)d_in[3];
    const float* kw     = (const float*)d_in[4];
    const float* kb     = (const float*)d_in[5];
    const float* vw     = (const float*)d_in[6];
    const float* vb     = (const float*)d_in[7];
    const float* ow     = (const float*)d_in[8];
    const float* ob     = (const float*)d_in[9];
    const float* ln_g   = (const float*)d_in[10];
    const float* ln_b   = (const float*)d_in[11];
    const float* out_w  = (const float*)d_in[12];
    const float* out_b  = (const float*)d_in[13];
    float* logits = (float*)d_out;

    float *x, *q, *k, *v, *ctx, *attn, *afrag, *wfrag;
    cudaGetSymbolAddress((void**)&x,     g_x);
    cudaGetSymbolAddress((void**)&q,     g_q);
    cudaGetSymbolAddress((void**)&k,     g_k);
    cudaGetSymbolAddress((void**)&v,     g_v);
    cudaGetSymbolAddress((void**)&ctx,   g_ctx);
    cudaGetSymbolAddress((void**)&attn,  g_attn);
    cudaGetSymbolAddress((void**)&afrag, g_afrag);
    cudaGetSymbolAddress((void**)&wfrag, g_wfrag);

    cudaFuncSetAttribute(gemm_mma,     cudaFuncAttributeMaxDynamicSharedMemorySize, GEMM_SMEM_BYTES);
    cudaFuncSetAttribute(gemm_mma_qkv, cudaFuncAttributeMaxDynamicSharedMemorySize, GEMM_SMEM_BYTES);
    cudaFuncSetAttribute(gemm_pre,     cudaFuncAttributeMaxDynamicSharedMemorySize, GEMM_SMEM_BYTES);

    // prelayout the logits weight once
    {
        dim3 gw(KC_D, NT_OUT);            // (32, 250)
        prelayout_W<<<gw, 256>>>(out_w, wfrag, VV);
    }

    embed_kernel<<<NROW, 256>>>(tokens, emb, x);

    dim3 gqkv(NROW / 128, DD / 128, 3);   // (16, 8, 3)
    dim3 gproj(NROW / 128, DD / 128);     // (16, 8)
    dim3 gattn(SS / 128, HH, BB);         // (8, 16, 2)

    for (int l = 0; l < LL; l++) {
        size_t wo = (size_t)l * DD * DD;
        size_t bo = (size_t)l * DD;
        gemm_mma_qkv<<<gqkv, 256, GEMM_SMEM_BYTES>>>(x, qw + wo, kw + wo, vw + wo,
                                                     qb + bo, kb + bo, vb + bo, q, k, v);
        attn_mma_kernel<<<gattn, 128>>>(q, k, v, ctx);
        gemm_mma<<<gproj, 256, GEMM_SMEM_BYTES>>>(ctx, ow + wo, ob + bo, attn, NROW, DD, DD);
        ln_res_kernel<<<NROW, 256>>>(x, attn, ln_g + bo, ln_b + bo);
    }

    // prelayout final activations, then fragment-major logits GEMM
    {
        dim3 ga(KC_D, MT_A);              // (32, 16)
        prelayout_A<<<ga, 256>>>(x, afrag, DD);
        dim3 gout(MT_A, NT_OUT);          // (16, 250)
        gemm_pre<<<gout, 256, GEMM_SMEM_BYTES>>>(afrag, wfrag, out_b, logits, VV, KC_D);
    }
}

// round 12
// speedup vs baseline: 2.0669x; 1.1726x over previous
#include <cuda_runtime.h>
#include <cstdint>
#include <math.h>

#define BB 2
#define SS 1024
#define DD 1024
#define HH 16
#define HD 64
#define LL 4
#define VV 32000
#define NROW (BB * SS)      // 2048
#define NT_OUT (VV / 128)   // 250 N-tiles for logits
#define NT_D   (DD / 128)   // 8 N-tiles for layer weights
#define MT_A   (NROW / 128) // 16 M-tiles
#define KC_D   (DD / 32)    // 32 K-chunks

// ---------------- scratch (static device globals; no allocs allowed) --------
__device__ float g_x[NROW * DD];
__device__ float g_q[NROW * DD];
__device__ float g_k[NROW * DD];
__device__ float g_v[NROW * DD];
__device__ float g_ctx[NROW * DD];
__device__ float g_attn[NROW * DD];
// fragment-major prelayout buffers
__device__ float g_afrag[MT_A * KC_D * 4096];                       // 8 MB
__device__ float g_wfrag[(size_t)NT_OUT * KC_D * 4096];             // 131 MB
__device__ float g_lwf[(size_t)LL * 4 * NT_D * KC_D * 4096];        // 64 MB

__device__ __forceinline__ float tf32r(float x) {
    float r; asm("cvt.rna.tf32.f32 %0, %1;" : "=f"(r) : "f"(x)); return r;
}

__device__ __forceinline__ void mma16n8k8(float* d, const float* a, float bx, float by) {
    asm volatile(
        "mma.sync.aligned.m16n8k8.row.col.f32.tf32.tf32.f32 "
        "{%0,%1,%2,%3}, {%4,%5,%6,%7}, {%8,%9}, {%0,%1,%2,%3};"
        : "+f"(d[0]), "+f"(d[1]), "+f"(d[2]), "+f"(d[3])
        : "r"(__float_as_uint(a[0])), "r"(__float_as_uint(a[1])),
          "r"(__float_as_uint(a[2])), "r"(__float_as_uint(a[3])),
          "r"(__float_as_uint(bx)), "r"(__float_as_uint(by)));
}

__device__ __forceinline__ uint32_t smem_u32(const void* p) {
    uint32_t a;
    asm("{ .reg .u64 t; cvta.to.shared.u64 t, %1; cvt.u32.u64 %0, t; }" : "=r"(a) : "l"(p));
    return a;
}
__device__ __forceinline__ void cpasync16(uint32_t dst, const void* src) {
    asm volatile("cp.async.cg.shared.global [%0], [%1], 16;" :: "r"(dst), "l"(src));
}
#define CP_COMMIT() asm volatile("cp.async.commit_group;" ::: "memory")
#define CP_WAIT(n)  asm volatile("cp.async.wait_group %0;" :: "n"(n) : "memory")

// =================== prelayout kernels (scatter ONCE into gmem) =============
// Exact fragment-major formulas verified in R6/R8.
__global__ void __launch_bounds__(256)
prelayout_A(const float* __restrict__ A, float* __restrict__ out, int K)
{
    const int kc = blockIdx.x;
    const int mt = blockIdx.y;
    const int t  = threadIdx.x;
    float* dst = out + ((size_t)mt * gridDim.x + kc) * 4096;
#pragma unroll
    for (int i = 0; i < 4; i++) {
        int idx = t + i * 256;
        int row = idx >> 3, c4 = idx & 7;
        int mi = row >> 4, m16 = row & 15;
        int ga = m16 & 7, rA = m16 >> 3;
        int ki = c4 >> 1, khi = c4 & 1;
        int base = ((mi * 4 + ki) * 32) * 4 + (rA + 2 * khi);
        float4 v = *(const float4*)(A + (size_t)(mt * 128 + row) * K + kc * 32 + c4 * 4);
        float vv[4] = {tf32r(v.x), tf32r(v.y), tf32r(v.z), tf32r(v.w)};
#pragma unroll
        for (int e = 0; e < 4; e++) {
            int lp = (ga * 4 + e) ^ ki;
            dst[base + lp * 4] = vv[e];
        }
    }
}

__global__ void __launch_bounds__(256)
prelayout_W(const float* __restrict__ W, float* __restrict__ out, int N)
{
    const int kc = blockIdx.x;
    const int nt = blockIdx.y;
    const int t  = threadIdx.x;
    float* dst = out + ((size_t)nt * gridDim.x + kc) * 4096;
#pragma unroll
    for (int i = 0; i < 4; i++) {
        int idx = t + i * 256;
        int rowk = idx >> 5, c4 = idx & 31;
        int n0 = c4 * 4;
        int ki = rowk >> 3, kk = rowk & 7;
        int tgb = kk & 3, hi = kk >> 2;
        int ni = n0 >> 3, g0 = n0 & 7;
        int swz = ((ni & 3) << 3) ^ (((ni >> 2) & 3) << 1);
        int ln0 = g0 * 4 + tgb;
        int base = ((ni * 4 + ki) * 32) * 2 + hi;
        float4 v = *(const float4*)(W + (size_t)(kc * 32 + rowk) * N + nt * 128 + n0);
        float vv[4] = {tf32r(v.x), tf32r(v.y), tf32r(v.z), tf32r(v.w)};
#pragma unroll
        for (int e = 0; e < 4; e++) {
            int lp = (ln0 + 4 * e) ^ swz;
            dst[base + lp * 2] = vv[e];
        }
    }
}

// ============== GEMM on prelaid operands, cp.async 3-stage ring =============
// stage slot s: A at sm + s*8192, B at sm + s*8192 + 4096 (floats)
#define PSTAGES 3
#define STAGE_FLOATS 8192
#define GEMM_PRE_SMEM_BYTES (PSTAGES * STAGE_FLOATS * 4)   // 96 KB

__device__ __forceinline__ void gemm_pre_core(
    const float* __restrict__ aSrc, const float* __restrict__ bSrc,
    const float* __restrict__ bias, float* __restrict__ C,
    int N, int nkc, int mt, int nt, float* sm)
{
    const int t    = threadIdx.x;
    const int lane = t & 31;
    const int wid  = t >> 5;
    const int g    = lane >> 2;
    const int tg   = lane & 3;
    const int wm   = (wid & 1) * 64;
    const int wn   = (wid >> 1) * 32;
    const uint32_t smb = smem_u32(sm);

    float acc[4][4][4];
#pragma unroll
    for (int mf = 0; mf < 4; mf++)
#pragma unroll
        for (int nf = 0; nf < 4; nf++)
#pragma unroll
            for (int r = 0; r < 4; r++) acc[mf][nf][r] = 0.0f;

    // issue copy of chunk c into slot c%PSTAGES
    auto issue = [&](int c) {
        uint32_t dstA = smb + (uint32_t)((c % PSTAGES) * STAGE_FLOATS) * 4u;
        uint32_t dstB = dstA + 4096u * 4u;
        const float* sa = aSrc + (size_t)c * 4096;
        const float* sb = bSrc + (size_t)c * 4096;
#pragma unroll
        for (int i = 0; i < 4; i++) {
            int o4 = (t + i * 256) * 4;
            cpasync16(dstA + (uint32_t)o4 * 4u, sa + o4);
            cpasync16(dstB + (uint32_t)o4 * 4u, sb + o4);
        }
        CP_COMMIT();
    };

    issue(0);
    issue(1);

    int bswz[4];
#pragma unroll
    for (int nf = 0; nf < 4; nf++) {
        int ni = (wid >> 1) * 4 + nf;
        bswz[nf] = lane ^ ((ni & 3) << 3) ^ (((ni >> 2) & 3) << 1);
    }

    for (int kt = 0; kt < nkc; kt++) {
        if (kt + 1 < nkc) { CP_WAIT(1); } else { CP_WAIT(0); }
        __syncthreads();
        if (kt + 2 < nkc) issue(kt + 2);   // writes slot (kt-1)%3, freed last iter

        const float* asb = sm + (kt % PSTAGES) * STAGE_FLOATS;
        const float* bsb = asb + 4096;
#pragma unroll
        for (int ki = 0; ki < 4; ki++) {
            float4 afv[4];
            float2 bfv[4];
#pragma unroll
            for (int mf = 0; mf < 4; mf++) {
                int mi = (wid & 1) * 4 + mf;
                afv[mf] = *(const float4*)(asb + ((mi * 4 + ki) * 32 + (lane ^ ki)) * 4);
            }
#pragma unroll
            for (int nf = 0; nf < 4; nf++) {
                int ni = (wid >> 1) * 4 + nf;
                bfv[nf] = *(const float2*)(bsb + ((ni * 4 + ki) * 32 + bswz[nf]) * 2);
            }
#pragma unroll
            for (int mf = 0; mf < 4; mf++)
#pragma unroll
                for (int nf = 0; nf < 4; nf++)
                    mma16n8k8(acc[mf][nf], (const float*)&afv[mf], bfv[nf].x, bfv[nf].y);
        }
    }

#pragma unroll
    for (int mf = 0; mf < 4; mf++) {
        const int r0 = mt * 128 + wm + mf * 16 + g;
        const int r1 = r0 + 8;
#pragma unroll
        for (int nf = 0; nf < 4; nf++) {
            const int col = nt * 128 + wn + nf * 8 + tg * 2;
            const float b0 = bias[col], b1 = bias[col + 1];
            float2 v0 = make_float2(acc[mf][nf][0] + b0, acc[mf][nf][1] + b1);
            float2 v1 = make_float2(acc[mf][nf][2] + b0, acc[mf][nf][3] + b1);
            *(float2*)(C + (size_t)r0 * N + col) = v0;
            *(float2*)(C + (size_t)r1 * N + col) = v1;
        }
    }
}

__global__ void __launch_bounds__(256, 2)
gemm_pre(const float* __restrict__ afrag, const float* __restrict__ wfrag,
         const float* __restrict__ bias, float* __restrict__ C,
         int N, int nkc)
{
    extern __shared__ float sm[];
    const int mt = blockIdx.x, nt = blockIdx.y;
    gemm_pre_core(afrag + (size_t)mt * nkc * 4096,
                  wfrag + (size_t)nt * nkc * 4096,
                  bias, C, N, nkc, mt, nt, sm);
}

// fused QKV on prelaid operands: grid.z selects projection
__global__ void __launch_bounds__(256, 2)
gemm_pre_qkv(const float* __restrict__ afrag,
             const float* __restrict__ qwf, const float* __restrict__ kwf,
             const float* __restrict__ vwf,
             const float* __restrict__ qb, const float* __restrict__ kb,
             const float* __restrict__ vb,
             float* __restrict__ qo, float* __restrict__ ko, float* __restrict__ vo)
{
    extern __shared__ float sm[];
    const int mt = blockIdx.x, nt = blockIdx.y;
    const float* wf   = (blockIdx.z == 0) ? qwf : (blockIdx.z == 1) ? kwf : vwf;
    const float* bias = (blockIdx.z == 0) ? qb  : (blockIdx.z == 1) ? kb  : vb;
    float*       C    = (blockIdx.z == 0) ? qo  : (blockIdx.z == 1) ? ko  : vo;
    gemm_pre_core(afrag + (size_t)mt * KC_D * 4096,
                  wf    + (size_t)nt * KC_D * 4096,
                  bias, C, DD, KC_D, mt, nt, sm);
}

// ---------------- embedding + sinusoidal positional encoding ---------------
__global__ void embed_kernel(const int* __restrict__ tokens,
                             const float* __restrict__ emb,
                             float* __restrict__ x)
{
    int row = blockIdx.x;
    int pos = row & (SS - 1);
    int tok = tokens[row];
    const float* e = emb + (size_t)tok * DD;
    float* xr = x + (size_t)row * DD;
    const float c = -logf(10000.0f) / (float)DD;
    for (int d = threadIdx.x; d < DD; d += blockDim.x) {
        int i = d >> 1;
        float ang = (float)pos * expf((float)(2 * i) * c);
        float pe = (d & 1) ? cosf(ang) : sinf(ang);
        xr[d] = e[d] + pe;
    }
}

// ============= tensor-core causal flash attention (tf32 mma) ================
__global__ void __launch_bounds__(128)
attn_mma_kernel(const float* __restrict__ Q, const float* __restrict__ K,
                const float* __restrict__ V, float* __restrict__ O)
{
    __shared__ __align__(16) float Ks[32][68];
    __shared__ __align__(16) float Vs[32][72];
    __shared__ __align__(16) float Ps[4][32][36];

    const int b  = blockIdx.z;
    const int h  = blockIdx.y;
    const int qb = blockIdx.x * 128;
    const int tid = threadIdx.x;
    const int w    = tid >> 5;
    const int lane = tid & 31;
    const int g    = lane >> 2;
    const int tg   = lane & 3;
    const size_t base = (size_t)(b * SS) * DD + (size_t)h * HD;

    float qf[2][8][4];
#pragma unroll
    for (int mf = 0; mf < 2; mf++) {
        const int r0 = qb + w * 32 + mf * 16 + g;
        const int r1 = r0 + 8;
#pragma unroll
        for (int k8 = 0; k8 < 8; k8++) {
            int k0 = k8 * 8;
            qf[mf][k8][0] = tf32r(Q[base + (size_t)r0 * DD + k0 + tg]     * 0.125f);
            qf[mf][k8][1] = tf32r(Q[base + (size_t)r1 * DD + k0 + tg]     * 0.125f);
            qf[mf][k8][2] = tf32r(Q[base + (size_t)r0 * DD + k0 + tg + 4] * 0.125f);
            qf[mf][k8][3] = tf32r(Q[base + (size_t)r1 * DD + k0 + tg + 4] * 0.125f);
        }
    }

    float oacc[2][8][4];
#pragma unroll
    for (int mf = 0; mf < 2; mf++)
#pragma unroll
        for (int nf = 0; nf < 8; nf++)
#pragma unroll
            for (int r = 0; r < 4; r++) oacc[mf][nf][r] = 0.0f;
    float mrow[2][2], lrow[2][2];
#pragma unroll
    for (int mf = 0; mf < 2; mf++) {
        mrow[mf][0] = -1e30f; mrow[mf][1] = -1e30f;
        lrow[mf][0] = 0.0f;   lrow[mf][1] = 0.0f;
    }

    const int qmax_w = qb + w * 32 + 31;
    const int kend = qb + 128;
    for (int kt = 0; kt < kend; kt += 32) {
#pragma unroll
        for (int i = 0; i < 4; i++) {
            int idx4 = tid + i * 128;
            int r = idx4 >> 4;
            int c = (idx4 & 15) * 4;
            size_t ga = base + (size_t)(kt + r) * DD + c;
            float4 kv = *(const float4*)(K + ga);
            float4 vv = *(const float4*)(V + ga);
            Ks[r][c]   = tf32r(kv.x); Ks[r][c+1] = tf32r(kv.y);
            Ks[r][c+2] = tf32r(kv.z); Ks[r][c+3] = tf32r(kv.w);
            Vs[r][c]   = tf32r(vv.x); Vs[r][c+1] = tf32r(vv.y);
            Vs[r][c+2] = tf32r(vv.z); Vs[r][c+3] = tf32r(vv.w);
        }
        __syncthreads();

        if (kt <= qmax_w) {
            float sacc[2][4][4];
#pragma unroll
            for (int mf = 0; mf < 2; mf++)
#pragma unroll
                for (int nf = 0; nf < 4; nf++)
#pragma unroll
                    for (int r = 0; r < 4; r++) sacc[mf][nf][r] = 0.0f;
#pragma unroll
            for (int k8 = 0; k8 < 8; k8++) {
                float2 bf[4];
#pragma unroll
                for (int nf = 0; nf < 4; nf++) {
                    bf[nf].x = Ks[nf * 8 + g][k8 * 8 + tg];
                    bf[nf].y = Ks[nf * 8 + g][k8 * 8 + tg + 4];
                }
#pragma unroll
                for (int mf = 0; mf < 2; mf++)
#pragma unroll
                    for (int nf = 0; nf < 4; nf++)
                        mma16n8k8(sacc[mf][nf], qf[mf][k8], bf[nf].x, bf[nf].y);
            }

#pragma unroll
            for (int mf = 0; mf < 2; mf++) {
                const int row0 = qb + w * 32 + mf * 16 + g;
                const int row1 = row0 + 8;
#pragma unroll
                for (int nf = 0; nf < 4; nf++) {
#pragma unroll
                    for (int e = 0; e < 2; e++) {
                        int key = kt + nf * 8 + tg * 2 + e;
                        if (key > row0) sacc[mf][nf][e]     = -1e30f;
                        if (key > row1) sacc[mf][nf][2 + e] = -1e30f;
                    }
                }
                float t0 = -1e30f, t1 = -1e30f;
#pragma unroll
                for (int nf = 0; nf < 4; nf++) {
                    t0 = fmaxf(t0, fmaxf(sacc[mf][nf][0], sacc[mf][nf][1]));
                    t1 = fmaxf(t1, fmaxf(sacc[mf][nf][2], sacc[mf][nf][3]));
                }
                t0 = fmaxf(t0, __shfl_xor_sync(0xFFFFFFFFu, t0, 1));
                t0 = fmaxf(t0, __shfl_xor_sync(0xFFFFFFFFu, t0, 2));
                t1 = fmaxf(t1, __shfl_xor_sync(0xFFFFFFFFu, t1, 1));
                t1 = fmaxf(t1, __shfl_xor_sync(0xFFFFFFFFu, t1, 2));
                float nm0 = fmaxf(mrow[mf][0], t0);
                float nm1 = fmaxf(mrow[mf][1], t1);
                float c0 = __expf(mrow[mf][0] - nm0);
                float c1 = __expf(mrow[mf][1] - nm1);
                mrow[mf][0] = nm0; mrow[mf][1] = nm1;

                float ps0 = 0.0f, ps1 = 0.0f;
#pragma unroll
                for (int nf = 0; nf < 4; nf++) {
#pragma unroll
                    for (int e = 0; e < 2; e++) {
                        float p0 = __expf(sacc[mf][nf][e]     - nm0);
                        float p1 = __expf(sacc[mf][nf][2 + e] - nm1);
                        sacc[mf][nf][e]     = p0;
                        sacc[mf][nf][2 + e] = p1;
                        ps0 += p0; ps1 += p1;
                    }
                }
                ps0 += __shfl_xor_sync(0xFFFFFFFFu, ps0, 1);
                ps0 += __shfl_xor_sync(0xFFFFFFFFu, ps0, 2);
                ps1 += __shfl_xor_sync(0xFFFFFFFFu, ps1, 1);
                ps1 += __shfl_xor_sync(0xFFFFFFFFu, ps1, 2);
                lrow[mf][0] = lrow[mf][0] * c0 + ps0;
                lrow[mf][1] = lrow[mf][1] * c1 + ps1;

#pragma unroll
                for (int nf2 = 0; nf2 < 8; nf2++) {
                    oacc[mf][nf2][0] *= c0; oacc[mf][nf2][1] *= c0;
                    oacc[mf][nf2][2] *= c1; oacc[mf][nf2][3] *= c1;
                }
#pragma unroll
                for (int nf = 0; nf < 4; nf++) {
                    float2 lo = make_float2(tf32r(sacc[mf][nf][0]), tf32r(sacc[mf][nf][1]));
                    float2 hi = make_float2(tf32r(sacc[mf][nf][2]), tf32r(sacc[mf][nf][3]));
                    *(float2*)&Ps[w][mf * 16 + g][nf * 8 + tg * 2]     = lo;
                    *(float2*)&Ps[w][mf * 16 + g + 8][nf * 8 + tg * 2] = hi;
                }
            }
            __syncwarp();

#pragma unroll
            for (int kk = 0; kk < 4; kk++) {
                float af[2][4];
#pragma unroll
                for (int mf = 0; mf < 2; mf++) {
                    af[mf][0] = Ps[w][mf * 16 + g][kk * 8 + tg];
                    af[mf][1] = Ps[w][mf * 16 + g + 8][kk * 8 + tg];
                    af[mf][2] = Ps[w][mf * 16 + g][kk * 8 + tg + 4];
                    af[mf][3] = Ps[w][mf * 16 + g + 8][kk * 8 + tg + 4];
                }
#pragma unroll
                for (int nf2 = 0; nf2 < 8; nf2++) {
                    float bx = Vs[kk * 8 + tg][nf2 * 8 + g];
                    float by = Vs[kk * 8 + tg + 4][nf2 * 8 + g];
#pragma unroll
                    for (int mf = 0; mf < 2; mf++)
                        mma16n8k8(oacc[mf][nf2], af[mf], bx, by);
                }
            }
        }
        __syncthreads();
    }

#pragma unroll
    for (int mf = 0; mf < 2; mf++) {
        const int row0 = qb + w * 32 + mf * 16 + g;
        const int row1 = row0 + 8;
        const float inv0 = 1.0f / lrow[mf][0];
        const float inv1 = 1.0f / lrow[mf][1];
#pragma unroll
        for (int nf2 = 0; nf2 < 8; nf2++) {
            const int col = nf2 * 8 + tg * 2;
            float2 v0 = make_float2(oacc[mf][nf2][0] * inv0, oacc[mf][nf2][1] * inv0);
            float2 v1 = make_float2(oacc[mf][nf2][2] * inv1, oacc[mf][nf2][3] * inv1);
            *(float2*)(O + base + (size_t)row0 * DD + col) = v0;
            *(float2*)(O + base + (size_t)row1 * DD + col) = v1;
        }
    }
}

// ---------------- residual add + layernorm (in place on x) ----------------
__global__ void __launch_bounds__(256)
ln_res_kernel(float* __restrict__ x, const float* __restrict__ res,
              const float* __restrict__ g, const float* __restrict__ beta)
{
    __shared__ float red[256];
    const int row = blockIdx.x;
    const int tid = threadIdx.x;
    float* xr = x + (size_t)row * DD;
    const float* rr = res + (size_t)row * DD;

    float y[4];
    float s = 0.0f;
#pragma unroll
    for (int i = 0; i < 4; i++) {
        int d = tid + i * 256;
        y[i] = xr[d] + rr[d];
        s += y[i];
    }
    red[tid] = s; __syncthreads();
    for (int off = 128; off > 0; off >>= 1) {
        if (tid < off) red[tid] += red[tid + off];
        __syncthreads();
    }
    float mu = red[0] * (1.0f / (float)DD);
    __syncthreads();

    float vs = 0.0f;
#pragma unroll
    for (int i = 0; i < 4; i++) {
        float d2 = y[i] - mu;
        vs += d2 * d2;
    }
    red[tid] = vs; __syncthreads();
    for (int off = 128; off > 0; off >>= 1) {
        if (tid < off) red[tid] += red[tid + off];
        __syncthreads();
    }
    float var = red[0] * (1.0f / (float)DD);
    float inv = rsqrtf(var + 1e-5f);

#pragma unroll
    for (int i = 0; i < 4; i++) {
        int d = tid + i * 256;
        xr[d] = (y[i] - mu) * inv * g[d] + beta[d];
    }
}

// ---------------------------------------------------------------------------
extern "C" void kernel_launch(void* const* d_in, const int* in_sizes, int n_in,
                              void* d_out, int out_size)
{
    const int*   tokens = (const int*)  d_in[0];
    const float* emb    = (const float*)d_in[1];
    const float* qw     = (const float*)d_in[2];
    const float* qb     = (const float*)d_in[3];
    const float* kw     = (const float*)d_in[4];
    const float* kb     = (const float*)d_in[5];
    const float* vw     = (const float*)d_in[6];
    const float* vb     = (const float*)d_in[7];
    const float* ow     = (const float*)d_in[8];
    const float* ob     = (const float*)d_in[9];
    const float* ln_g   = (const float*)d_in[10];
    const float* ln_b   = (const float*)d_in[11];
    const float* out_w  = (const float*)d_in[12];
    const float* out_b  = (const float*)d_in[13];
    float* logits = (float*)d_out;

    float *x, *q, *k, *v, *ctx, *attn, *afrag, *wfrag, *lwf;
    cudaGetSymbolAddress((void**)&x,     g_x);
    cudaGetSymbolAddress((void**)&q,     g_q);
    cudaGetSymbolAddress((void**)&k,     g_k);
    cudaGetSymbolAddress((void**)&v,     g_v);
    cudaGetSymbolAddress((void**)&ctx,   g_ctx);
    cudaGetSymbolAddress((void**)&attn,  g_attn);
    cudaGetSymbolAddress((void**)&afrag, g_afrag);
    cudaGetSymbolAddress((void**)&wfrag, g_wfrag);
    cudaGetSymbolAddress((void**)&lwf,   g_lwf);

    cudaFuncSetAttribute(gemm_pre,     cudaFuncAttributeMaxDynamicSharedMemorySize, GEMM_PRE_SMEM_BYTES);
    cudaFuncSetAttribute(gemm_pre_qkv, cudaFuncAttributeMaxDynamicSharedMemorySize, GEMM_PRE_SMEM_BYTES);

    const size_t WMAT = (size_t)NT_D * KC_D * 4096;   // floats per layer matrix

    // ---- one-time prelayouts (inside timed call; amortized vs GEMM savings)
    {
        dim3 gw(KC_D, NT_OUT);
        prelayout_W<<<gw, 256>>>(out_w, wfrag, VV);
        dim3 gl(KC_D, NT_D);
        for (int l = 0; l < LL; l++) {
            size_t wo = (size_t)l * DD * DD;
            prelayout_W<<<gl, 256>>>(qw + wo, lwf + (size_t)(l * 4 + 0) * WMAT, DD);
            prelayout_W<<<gl, 256>>>(kw + wo, lwf + (size_t)(l * 4 + 1) * WMAT, DD);
            prelayout_W<<<gl, 256>>>(vw + wo, lwf + (size_t)(l * 4 + 2) * WMAT, DD);
            prelayout_W<<<gl, 256>>>(ow + wo, lwf + (size_t)(l * 4 + 3) * WMAT, DD);
        }
    }

    embed_kernel<<<NROW, 256>>>(tokens, emb, x);

    dim3 gpreA(KC_D, MT_A);               // (32, 16)
    dim3 gqkv(MT_A, NT_D, 3);             // (16, 8, 3)
    dim3 gproj(MT_A, NT_D);               // (16, 8)
    dim3 gattn(SS / 128, HH, BB);         // (8, 16, 2)

    for (int l = 0; l < LL; l++) {
        size_t bo = (size_t)l * DD;
        prelayout_A<<<gpreA, 256>>>(x, afrag, DD);
        gemm_pre_qkv<<<gqkv, 256, GEMM_PRE_SMEM_BYTES>>>(
            afrag,
            lwf + (size_t)(l * 4 + 0) * WMAT,
            lwf + (size_t)(l * 4 + 1) * WMAT,
            lwf + (size_t)(l * 4 + 2) * WMAT,
            qb + bo, kb + bo, vb + bo, q, k, v);
        attn_mma_kernel<<<gattn, 128>>>(q, k, v, ctx);
        prelayout_A<<<gpreA, 256>>>(ctx, afrag, DD);
        gemm_pre<<<gproj, 256, GEMM_PRE_SMEM_BYTES>>>(
            afrag, lwf + (size_t)(l * 4 + 3) * WMAT, ob + bo, attn, DD, KC_D);
        ln_res_kernel<<<NROW, 256>>>(x, attn, ln_g + bo, ln_b + bo);
    }

    // final logits
    prelayout_A<<<gpreA, 256>>>(x, afrag, DD);
    dim3 gout(MT_A, NT_OUT);              // (16, 250)
    gemm_pre<<<gout, 256, GEMM_PRE_SMEM_BYTES>>>(afrag, wfrag, out_b, logits, VV, KC_D);
}